// round 9
// baseline (speedup 1.0000x reference)
#include <cuda_runtime.h>
#include <math.h>
#include <stdint.h>

#define NFEAT 64
#define DIM   256
#define NHEAD 8
#define HDIM  32
#define QS    36
#define ATS   68

// smem floats: Axf(tf32) 16384 | kt 2048 | qh 2304 | vh 2048 | att 4352 | red 256
#define OFF_KT   16384
#define OFF_QH   (OFF_KT + 2048)
#define OFF_VH   (OFF_QH + NFEAT*QS)
#define OFF_ATT  (OFF_VH + 2048)
#define OFF_RED  (OFF_ATT + NFEAT*ATS)
#define SMEM_FLOATS (OFF_RED + 256)   // 27392 -> 109,568 B

// pre-converted tf32 weight fragments (written by prep_kernel each launch)
// WPF: [h 8][ch 8][ks2 4][nt 12][lane 32][2]   (Wq|Wk|Wv per-head slices)
// W1F: [h 8][nc 2][ks 4][nt 16][lane 32][2]
__device__ uint32_t WPF[8*8*4*12*32*2];   // 196,608 words
__device__ uint32_t W1F[8*2*4*16*32*2];   //  65,536 words

typedef unsigned long long u64;

__device__ __forceinline__ void ffma2(u64& d, u64 a, u64 b) {
    asm("fma.rn.f32x2 %0, %1, %2, %0;" : "+l"(d) : "l"(a), "l"(b));
}
__device__ __forceinline__ u64 dup2(float v) {
    u64 r; asm("mov.b64 %0, {%1, %1};" : "=l"(r) : "f"(v)); return r;
}
__device__ __forceinline__ float2 unpk(u64 v) {
    float lo, hi; asm("mov.b64 {%0, %1}, %2;" : "=f"(lo), "=f"(hi) : "l"(v));
    return make_float2(lo, hi);
}
__device__ __forceinline__ uint32_t f2tf(float x) {
    uint32_t r; asm("cvt.rna.tf32.f32 %0, %1;" : "=r"(r) : "f"(x)); return r;
}
__device__ __forceinline__ void mma_tf32(float4& d,
    uint32_t a0, uint32_t a1, uint32_t a2, uint32_t a3,
    uint32_t b0, uint32_t b1)
{
    asm("mma.sync.aligned.m16n8k8.row.col.f32.tf32.tf32.f32 "
        "{%0,%1,%2,%3}, {%4,%5,%6,%7}, {%8,%9}, {%0,%1,%2,%3};"
        : "+f"(d.x), "+f"(d.y), "+f"(d.z), "+f"(d.w)
        : "r"(a0), "r"(a1), "r"(a2), "r"(a3), "r"(b0), "r"(b1));
}

// ---------------- prep: weights -> tf32 B-fragment order -----------------
__global__ __launch_bounds__(256)
void prep_kernel(const float* __restrict__ Wq, const float* __restrict__ Wk,
                 const float* __restrict__ Wv, const float* __restrict__ W1)
{
    int id = blockIdx.x * 256 + threadIdx.x;   // one per (…,lane) b0/b1 pair
    if (id < 98304) {                          // proj: 8*8*4*12*32
        int lane = id & 31;
        int g    = id >> 5;
        int nt   = g % 12;
        int ks2  = (g / 12) & 3;
        int ch   = (g / 48) & 7;
        int h    = g / 384;
        int mat  = nt >> 2;
        const float* W = (mat == 0) ? Wq : (mat == 1) ? Wk : Wv;
        int n = h * HDIM + (nt & 3) * 8 + (lane >> 2);
        int k = ch * 32 + ks2 * 8 + (lane & 3);
        uint2 v = make_uint2(f2tf(W[k * DIM + n]), f2tf(W[(k + 4) * DIM + n]));
        *(uint2*)&WPF[id * 2] = v;
    } else {                                   // W1: 8*2*4*16*32
        int j    = id - 98304;
        int lane = j & 31;
        int g    = j >> 5;
        int nt   = g % 16;
        int ks   = (g / 16) & 3;
        int nc   = (g / 64) & 1;
        int h    = g / 128;
        int n = nc * 128 + nt * 8 + (lane >> 2);
        int k = h * HDIM + ks * 8 + (lane & 3);
        uint2 v = make_uint2(f2tf(W1[k * DIM + n]), f2tf(W1[(k + 4) * DIM + n]));
        *(uint2*)&W1F[j * 2] = v;
    }
}

// ---------------- main ----------------
__global__ __launch_bounds__(256, 2)
void autoint_kernel(const float* __restrict__ x,
                    const float* __restrict__ bq, const float* __restrict__ bk,
                    const float* __restrict__ bv, const float* __restrict__ b1,
                    const float* __restrict__ W2, const float* __restrict__ b2,
                    float* __restrict__ out)
{
    extern __shared__ float sm[];
    uint32_t* axf_u = (uint32_t*)sm;      // x as tf32 A-fragments
    float* kt  = sm + OFF_KT;             // k transposed; reused as z frags
    float* qh  = sm + OFF_QH;
    float* vh  = sm + OFF_VH;
    float* att = sm + OFF_ATT;
    float* red = sm + OFF_RED;
    uint32_t* kt_u = (uint32_t*)kt;

    const int t = threadIdx.x;
    const int b = blockIdx.x;
    const float* xg = x + (size_t)b * (NFEAT * DIM);

    const int lane = t & 31;
    const int grp  = lane >> 2;
    const int tig  = lane & 3;
    const int w    = t >> 5;
    const int mt   = w & 3;
    const int half = w >> 2;

    // ---- phase 0: x -> tf32 A-fragment order ----
    {
        const float4* xg4 = (const float4*)xg;
#pragma unroll
        for (int n = t; n < NFEAT * DIM / 4; n += 256) {
            float4 v = xg4[n];
            int r   = n >> 6;
            int c4  = (n & 63) << 2;
            int rmt = r >> 4, rgr = r & 7, hi8 = (r >> 3) & 1;
            int ks  = c4 >> 3, chi = (c4 >> 2) & 1;
            uint32_t* d = axf_u + (((rmt * 32 + ks) * 32 + rgr * 4) << 2)
                          + hi8 + (chi << 1);
            d[0] = f2tf(v.x); d[4] = f2tf(v.y); d[8] = f2tf(v.z); d[12] = f2tf(v.w);
        }
    }

    const float inv_sqrt_d = 0.17677669529663687f;

    float4 facc4[16];
#pragma unroll
    for (int i = 0; i < 16; i++) facc4[i] = make_float4(0.f, 0.f, 0.f, 0.f);

    for (int h = 0; h < NHEAD; h++) {
        const int hd = h * HDIM;
        __syncthreads();   // loop top: axf visible (h=0); kt/qh/vh/att free

        // ===== QKV projection: B fragments direct from WPF (gmem) =====
        float4 D[6];
#pragma unroll
        for (int i = 0; i < 6; i++) D[i] = make_float4(0.f, 0.f, 0.f, 0.f);
        {
            const uint2* wpf = (const uint2*)WPF + (size_t)h * (8*4*12*32);
#pragma unroll 2
            for (int ch = 0; ch < 8; ch++) {
#pragma unroll
                for (int ks2 = 0; ks2 < 4; ks2++) {
                    uint4 av = *(const uint4*)&axf_u[((mt * 32 + ch * 4 + ks2) * 32 + lane) << 2];
                    const uint2* bp = wpf + ((ch * 4 + ks2) * 12 + half * 6) * 32 + lane;
#pragma unroll
                    for (int nt = 0; nt < 6; nt++) {
                        uint2 bb = bp[nt * 32];
                        mma_tf32(D[nt], av.x, av.y, av.z, av.w, bb.x, bb.y);
                    }
                }
            }
        }
        // scatter D + bias into qh / kt / vh
        {
            const int r0 = mt * 16 + grp, r1 = r0 + 8;
#pragma unroll
            for (int nt = 0; nt < 6; nt++) {
                const int n   = half * 48 + nt * 8 + 2 * tig;
                const int mat = n >> 5;
                const int mc  = n & 31;
                const float* bp = (mat == 0) ? bq : (mat == 1) ? bk : bv;
                float2 bb = *(const float2*)&bp[hd + mc];
                float4 d = D[nt];
                if (mat == 0) {
                    *(float2*)&qh[r0 * QS + mc] = make_float2(d.x + bb.x, d.y + bb.y);
                    *(float2*)&qh[r1 * QS + mc] = make_float2(d.z + bb.x, d.w + bb.y);
                } else if (mat == 1) {
                    kt[mc * 64 + r0]       = d.x + bb.x;
                    kt[(mc + 1) * 64 + r0] = d.y + bb.y;
                    kt[mc * 64 + r1]       = d.z + bb.x;
                    kt[(mc + 1) * 64 + r1] = d.w + bb.y;
                } else {
                    *(float2*)&vh[r0 * HDIM + mc] = make_float2(d.x + bb.x, d.y + bb.y);
                    *(float2*)&vh[r1 * HDIM + mc] = make_float2(d.z + bb.x, d.w + bb.y);
                }
            }
        }
        __syncthreads();

        // ===== scores (fp32x2): att = q.k^T / sqrt(d) =====
        {
            const int i0 = (t >> 4) << 2;
            const int j0 = (t & 15) << 2;
            u64 a[4][2];
#pragma unroll
            for (int r = 0; r < 4; r++) { a[r][0] = 0ull; a[r][1] = 0ull; }
#pragma unroll
            for (int kk = 0; kk < HDIM; kk += 4) {
                ulonglong2 k0 = *(const ulonglong2*)&kt[(kk+0)*64 + j0];
                ulonglong2 k1 = *(const ulonglong2*)&kt[(kk+1)*64 + j0];
                ulonglong2 k2 = *(const ulonglong2*)&kt[(kk+2)*64 + j0];
                ulonglong2 k3 = *(const ulonglong2*)&kt[(kk+3)*64 + j0];
                float4 q0 = *(const float4*)&qh[(i0+0)*QS + kk];
                float4 q1 = *(const float4*)&qh[(i0+1)*QS + kk];
                float4 q2 = *(const float4*)&qh[(i0+2)*QS + kk];
                float4 q3 = *(const float4*)&qh[(i0+3)*QS + kk];
#pragma unroll
                for (int r = 0; r < 4; r++) {
                    float4 qr = (r==0) ? q0 : (r==1) ? q1 : (r==2) ? q2 : q3;
                    u64 d;
                    d = dup2(qr.x); ffma2(a[r][0], d, k0.x); ffma2(a[r][1], d, k0.y);
                    d = dup2(qr.y); ffma2(a[r][0], d, k1.x); ffma2(a[r][1], d, k1.y);
                    d = dup2(qr.z); ffma2(a[r][0], d, k2.x); ffma2(a[r][1], d, k2.y);
                    d = dup2(qr.w); ffma2(a[r][0], d, k3.x); ffma2(a[r][1], d, k3.y);
                }
            }
#pragma unroll
            for (int r = 0; r < 4; r++) {
                float2 lo = unpk(a[r][0]);
                float2 hi = unpk(a[r][1]);
                *(float4*)&att[(i0+r)*ATS + j0] = make_float4(
                    lo.x*inv_sqrt_d, lo.y*inv_sqrt_d, hi.x*inv_sqrt_d, hi.y*inv_sqrt_d);
            }
        }
        __syncthreads();

        // ---- softmax: 2 threads per row ----
        if (t < 128) {
            const int row = t >> 1;
            const int hf  = (t & 1) << 5;
            float* rp = att + row * ATS + hf;
            float m = rp[0];
#pragma unroll
            for (int j = 1; j < 32; j++) m = fmaxf(m, rp[j]);
            m = fmaxf(m, __shfl_xor_sync(0xFFFFFFFF, m, 1));
            float s = 0.f;
#pragma unroll
            for (int j = 0; j < 32; j++) { float e = __expf(rp[j] - m); rp[j] = e; s += e; }
            s += __shfl_xor_sync(0xFFFFFFFF, s, 1);
            float inv = 1.f / s;
#pragma unroll
            for (int j = 0; j < 32; j++) rp[j] *= inv;
        }
        __syncthreads();

        // ===== z = att @ vh -> kt as tf32 A-fragments (conflict-free) =====
        if (t < 128) {
            const int ks4  = t & 3;
            const int grps = (t >> 2) & 7;
            const int rmts = t >> 5;
            const int r0 = rmts * 16 + grps, r1 = r0 + 8;
            const int c8 = ks4 * 8;
            u64 a0[4] = {0ull,0ull,0ull,0ull};
            u64 a1[4] = {0ull,0ull,0ull,0ull};
#pragma unroll 4
            for (int j = 0; j < NFEAT; j += 2) {
                float2 p0 = *(const float2*)&att[r0 * ATS + j];
                float2 p1 = *(const float2*)&att[r1 * ATS + j];
#pragma unroll
                for (int jj = 0; jj < 2; jj++) {
                    ulonglong2 vA = *(const ulonglong2*)&vh[(j+jj)*HDIM + c8];
                    ulonglong2 vB = *(const ulonglong2*)&vh[(j+jj)*HDIM + c8 + 4];
                    u64 d0 = dup2(jj ? p0.y : p0.x);
                    u64 d1 = dup2(jj ? p1.y : p1.x);
                    ffma2(a0[0], d0, vA.x); ffma2(a0[1], d0, vA.y);
                    ffma2(a0[2], d0, vB.x); ffma2(a0[3], d0, vB.y);
                    ffma2(a1[0], d1, vA.x); ffma2(a1[1], d1, vA.y);
                    ffma2(a1[2], d1, vB.x); ffma2(a1[3], d1, vB.y);
                }
            }
            float z0[8], z1[8];
#pragma unroll
            for (int q = 0; q < 4; q++) {
                float2 f0 = unpk(a0[q]); z0[2*q] = f0.x; z0[2*q+1] = f0.y;
                float2 f1 = unpk(a1[q]); z1[2*q] = f1.x; z1[2*q+1] = f1.y;
            }
            const uint32_t base = (rmts * 4 + ks4) * 128 + grps * 16;
#pragma unroll
            for (int i = 0; i < 4; i++) {
                uint4 val = make_uint4(f2tf(z0[i]), f2tf(z1[i]),
                                       f2tf(z0[i+4]), f2tf(z1[i+4]));
                *(uint4*)&kt_u[base + ((i ^ ks4) << 2)] = val;
            }
        }
        __syncthreads();

        // ===== facc += z @ W1[hd:hd+32,:] : B fragments direct from W1F =====
        {
            const uint2* w1f = (const uint2*)W1F + (size_t)h * (2*4*16*32);
#pragma unroll
            for (int nc = 0; nc < 2; nc++) {
#pragma unroll
                for (int ks = 0; ks < 4; ks++) {
                    uint4 za = *(const uint4*)&kt_u[(mt * 4 + ks) * 128 + grp * 16
                                                    + ((tig ^ ks) << 2)];
                    const uint2* bp = w1f + ((nc * 4 + ks) * 16 + half * 8) * 32 + lane;
#pragma unroll
                    for (int nt = 0; nt < 8; nt++) {
                        uint2 bb = bp[nt * 32];
                        mma_tf32(facc4[nc * 8 + nt], za.x, za.y, za.z, za.w, bb.x, bb.y);
                    }
                }
            }
        }
        // loop-top sync protects kt/qh/vh/att reuse
    }

    // ===== epilogue: f = relu(facc + b1 + x); dot W2 (x exact from gmem) ====
    {
        const int r0 = mt * 16 + grp, r1 = r0 + 8;
        float part = 0.f;
#pragma unroll
        for (int fi = 0; fi < 16; fi++) {
            int nc = fi >> 3, nt = fi & 7;
            int n  = nc * 128 + half * 64 + nt * 8 + 2 * tig;
            float2 b1v = *(const float2*)&b1[n];
            float2 x0  = *(const float2*)&xg[r0 * DIM + n];
            float2 x1  = *(const float2*)&xg[r1 * DIM + n];
            float2 w20 = *(const float2*)&W2[r0 * DIM + n];
            float2 w21 = *(const float2*)&W2[r1 * DIM + n];
            float4 d = facc4[fi];
            float f0 = fmaxf(d.x + b1v.x + x0.x, 0.f);
            float f1 = fmaxf(d.y + b1v.y + x0.y, 0.f);
            float f2 = fmaxf(d.z + b1v.x + x1.x, 0.f);
            float f3 = fmaxf(d.w + b1v.y + x1.y, 0.f);
            part += f0 * w20.x + f1 * w20.y + f2 * w21.x + f3 * w21.y;
        }
        red[t] = part;
    }
    __syncthreads();

#pragma unroll
    for (int s = 128; s > 0; s >>= 1) {
        if (t < s) red[t] += red[t + s];
        __syncthreads();
    }
    if (t == 0) {
        out[b] = 1.f / (1.f + __expf(-(red[0] + b2[0])));
    }
}

extern "C" void kernel_launch(void* const* d_in, const int* in_sizes, int n_in,
                              void* d_out, int out_size)
{
    const float* x  = (const float*)d_in[0];
    const float* Wq = (const float*)d_in[1];
    const float* bq = (const float*)d_in[2];
    const float* Wk = (const float*)d_in[3];
    const float* bk = (const float*)d_in[4];
    const float* Wv = (const float*)d_in[5];
    const float* bv = (const float*)d_in[6];
    const float* W1 = (const float*)d_in[7];
    const float* b1 = (const float*)d_in[8];
    const float* W2 = (const float*)d_in[9];
    const float* b2 = (const float*)d_in[10];
    float* out = (float*)d_out;

    // 131072 fragment pairs -> 512 blocks x 256 threads
    prep_kernel<<<512, 256>>>(Wq, Wk, Wv, W1);

    const int smem_bytes = SMEM_FLOATS * (int)sizeof(float); // 109,568 B -> 2 CTAs/SM
    cudaFuncSetAttribute(autoint_kernel,
                         cudaFuncAttributeMaxDynamicSharedMemorySize, smem_bytes);
    autoint_kernel<<<8192, 256, smem_bytes>>>(x, bq, bk, bv, b1, W2, b2, out);
}

// round 10
// speedup vs baseline: 1.3467x; 1.3467x over previous
#include <cuda_runtime.h>
#include <math.h>
#include <stdint.h>

#define NFEAT 64
#define DIM   256
#define NHEAD 8
#define HDIM  32
#define QS    36
#define ATS   68

// smem floats: Axf(tf32) 16384 | kt 2048 | qh 2304 | vh 2048 | att 4352 | red 256
#define OFF_KT   16384
#define OFF_QH   (OFF_KT + 2048)       // 18432
#define OFF_VH   (OFF_QH + NFEAT*QS)   // 20736
#define OFF_ATT  (OFF_VH + 2048)       // 22784
#define OFF_RED  (OFF_ATT + NFEAT*ATS) // 27136
#define SMEM_FLOATS (OFF_RED + 256)    // 27392 -> 109,568 B

// proj staging: 3 buffers x 3072 words in the dead kt..att region
#define SB0 16384
#define SB1 (16384 + 3072)
#define SB2 (16384 + 6144)             // ends 25600 < OFF_RED
// W1 staging: 2 x 4096 words
#define WB0 OFF_ATT                    // 22784..26879 (att+part of red? 26880<27136 ok)
#define WB1 OFF_QH                     // 18432..22527 (qh+vh)

// pre-converted tf32 weight fragments (written by prep_kernel each launch)
// WPF: [h 8][ch 8][ks2 4][nt 12][lane 32][2]
// W1F: [h 8][nc 2][ks 4][nt 16][lane 32][2]
__device__ uint32_t WPF[8*8*4*12*32*2];   // 196,608 words
__device__ uint32_t W1F[8*2*4*16*32*2];   //  65,536 words

typedef unsigned long long u64;

__device__ __forceinline__ void ffma2(u64& d, u64 a, u64 b) {
    asm("fma.rn.f32x2 %0, %1, %2, %0;" : "+l"(d) : "l"(a), "l"(b));
}
__device__ __forceinline__ u64 dup2(float v) {
    u64 r; asm("mov.b64 %0, {%1, %1};" : "=l"(r) : "f"(v)); return r;
}
__device__ __forceinline__ float2 unpk(u64 v) {
    float lo, hi; asm("mov.b64 {%0, %1}, %2;" : "=f"(lo), "=f"(hi) : "l"(v));
    return make_float2(lo, hi);
}
__device__ __forceinline__ uint32_t f2tf(float x) {
    uint32_t r; asm("cvt.rna.tf32.f32 %0, %1;" : "=r"(r) : "f"(x)); return r;
}
__device__ __forceinline__ void mma_tf32(float4& d,
    uint32_t a0, uint32_t a1, uint32_t a2, uint32_t a3,
    uint32_t b0, uint32_t b1)
{
    asm("mma.sync.aligned.m16n8k8.row.col.f32.tf32.tf32.f32 "
        "{%0,%1,%2,%3}, {%4,%5,%6,%7}, {%8,%9}, {%0,%1,%2,%3};"
        : "+f"(d.x), "+f"(d.y), "+f"(d.z), "+f"(d.w)
        : "r"(a0), "r"(a1), "r"(a2), "r"(a3), "r"(b0), "r"(b1));
}
__device__ __forceinline__ uint32_t s2u(const void* p) {
    uint32_t a;
    asm("{ .reg .u64 t; cvta.to.shared.u64 t, %1; cvt.u32.u64 %0, t; }"
        : "=r"(a) : "l"(p));
    return a;
}
#define CPA16(dst, src) \
    asm volatile("cp.async.cg.shared.global [%0], [%1], 16;" :: "r"(dst), "l"(src))
#define CPCOMMIT() asm volatile("cp.async.commit_group;" ::: "memory")
#define CPWAIT1()  asm volatile("cp.async.wait_group 1;"  ::: "memory")
#define CPWAIT0()  asm volatile("cp.async.wait_group 0;"  ::: "memory")

// ---------------- prep: weights -> tf32 B-fragment order -----------------
__global__ __launch_bounds__(256)
void prep_kernel(const float* __restrict__ Wq, const float* __restrict__ Wk,
                 const float* __restrict__ Wv, const float* __restrict__ W1)
{
    int id = blockIdx.x * 256 + threadIdx.x;
    if (id < 98304) {                          // proj: 8*8*4*12*32
        int lane = id & 31;
        int g    = id >> 5;
        int nt   = g % 12;
        int ks2  = (g / 12) & 3;
        int ch   = (g / 48) & 7;
        int h    = g / 384;
        int mat  = nt >> 2;
        const float* W = (mat == 0) ? Wq : (mat == 1) ? Wk : Wv;
        int n = h * HDIM + (nt & 3) * 8 + (lane >> 2);
        int k = ch * 32 + ks2 * 8 + (lane & 3);
        uint2 v = make_uint2(f2tf(W[k * DIM + n]), f2tf(W[(k + 4) * DIM + n]));
        *(uint2*)&WPF[id * 2] = v;
    } else {                                   // W1: 8*2*4*16*32
        int j    = id - 98304;
        int lane = j & 31;
        int g    = j >> 5;
        int nt   = g % 16;
        int ks   = (g / 16) & 3;
        int nc   = (g / 64) & 1;
        int h    = g / 128;
        int n = nc * 128 + nt * 8 + (lane >> 2);
        int k = h * HDIM + ks * 8 + (lane & 3);
        uint2 v = make_uint2(f2tf(W1[k * DIM + n]), f2tf(W1[(k + 4) * DIM + n]));
        *(uint2*)&W1F[j * 2] = v;
    }
}

// ---------------- main ----------------
__global__ __launch_bounds__(256, 2)
void autoint_kernel(const float* __restrict__ x,
                    const float* __restrict__ bq, const float* __restrict__ bk,
                    const float* __restrict__ bv, const float* __restrict__ b1,
                    const float* __restrict__ W2, const float* __restrict__ b2,
                    float* __restrict__ out)
{
    extern __shared__ float sm[];
    uint32_t* smw   = (uint32_t*)sm;
    uint32_t* axf_u = smw;                // x as tf32 A-fragments
    float* kt  = sm + OFF_KT;             // k transposed; reused as z frags
    float* qh  = sm + OFF_QH;
    float* vh  = sm + OFF_VH;
    float* att = sm + OFF_ATT;
    float* red = sm + OFF_RED;
    uint32_t* kt_u = (uint32_t*)kt;
    const uint32_t smu = s2u(sm);

    const int t = threadIdx.x;
    const int b = blockIdx.x;
    const float* xg = x + (size_t)b * (NFEAT * DIM);

    const int lane = t & 31;
    const int grp  = lane >> 2;
    const int tig  = lane & 3;
    const int w    = t >> 5;
    const int mt   = w & 3;
    const int half = w >> 2;

    // ---- phase 0: x -> tf32 A-fragment order ----
    {
        const float4* xg4 = (const float4*)xg;
#pragma unroll
        for (int n = t; n < NFEAT * DIM / 4; n += 256) {
            float4 v = xg4[n];
            int r   = n >> 6;
            int c4  = (n & 63) << 2;
            int rmt = r >> 4, rgr = r & 7, hi8 = (r >> 3) & 1;
            int ks  = c4 >> 3, chi = (c4 >> 2) & 1;
            uint32_t* d = axf_u + (((rmt * 32 + ks) * 32 + rgr * 4) << 2)
                          + hi8 + (chi << 1);
            d[0] = f2tf(v.x); d[4] = f2tf(v.y); d[8] = f2tf(v.z); d[12] = f2tf(v.w);
        }
    }

    const float inv_sqrt_d = 0.17677669529663687f;

    float4 facc4[16];
#pragma unroll
    for (int i = 0; i < 16; i++) facc4[i] = make_float4(0.f, 0.f, 0.f, 0.f);

    const uint4* wpf4 = (const uint4*)WPF;   // 768 uint4 per (h,ch)
    const uint4* w1f4 = (const uint4*)W1F;   // 2048 uint4 per h

    for (int h = 0; h < NHEAD; h++) {
        const int hd = h * HDIM;
        __syncthreads();   // loop top: axf visible (h=0); stage region free

        // ===== QKV projection: staged B fragments, triple-buffered cp.async
        const int sbuf[3] = {SB0, SB1, SB2};
        // prologue: stage ch0, ch1
#pragma unroll
        for (int c = 0; c < 2; c++) {
            const uint4* src = wpf4 + (h * 8 + c) * 768;
#pragma unroll
            for (int j = 0; j < 3; j++) {
                int idx = t + j * 256;
                CPA16(smu + ((sbuf[c] + idx * 4) << 2), src + idx);
            }
            CPCOMMIT();
        }

        float4 D[6];
#pragma unroll
        for (int i = 0; i < 6; i++) D[i] = make_float4(0.f, 0.f, 0.f, 0.f);

        for (int ch = 0; ch < 8; ch++) {
            CPWAIT1();          // chunk ch copy complete (ch+1 may be pending)
            __syncthreads();    // visibility + prev-buffer readers done
            if (ch + 2 < 8) {   // stage ch+2 into buffer (ch+2)%3
                const uint4* src = wpf4 + (h * 8 + ch + 2) * 768;
                const int bofs = sbuf[(ch + 2) % 3];
#pragma unroll
                for (int j = 0; j < 3; j++) {
                    int idx = t + j * 256;
                    CPA16(smu + ((bofs + idx * 4) << 2), src + idx);
                }
            }
            CPCOMMIT();         // unconditional: keeps group accounting aligned
            const uint32_t* bw = smw + sbuf[ch % 3];
#pragma unroll
            for (int ks2 = 0; ks2 < 4; ks2++) {
                uint4 av = *(const uint4*)&axf_u[((mt * 32 + ch * 4 + ks2) * 32 + lane) << 2];
                const uint32_t* bp = bw + (((ks2 * 12 + half * 6) * 32 + lane) << 1);
#pragma unroll
                for (int nt = 0; nt < 6; nt++) {
                    uint2 bb = *(const uint2*)(bp + nt * 64);
                    mma_tf32(D[nt], av.x, av.y, av.z, av.w, bb.x, bb.y);
                }
            }
        }
        __syncthreads();   // all warps done with staged buffers before scatter

        // scatter D + bias into qh / kt / vh
        {
            const int r0 = mt * 16 + grp, r1 = r0 + 8;
#pragma unroll
            for (int nt = 0; nt < 6; nt++) {
                const int n   = half * 48 + nt * 8 + 2 * tig;
                const int mat = n >> 5;
                const int mc  = n & 31;
                const float* bp = (mat == 0) ? bq : (mat == 1) ? bk : bv;
                float2 bb = *(const float2*)&bp[hd + mc];
                float4 d = D[nt];
                if (mat == 0) {
                    *(float2*)&qh[r0 * QS + mc] = make_float2(d.x + bb.x, d.y + bb.y);
                    *(float2*)&qh[r1 * QS + mc] = make_float2(d.z + bb.x, d.w + bb.y);
                } else if (mat == 1) {
                    kt[mc * 64 + r0]       = d.x + bb.x;
                    kt[(mc + 1) * 64 + r0] = d.y + bb.y;
                    kt[mc * 64 + r1]       = d.z + bb.x;
                    kt[(mc + 1) * 64 + r1] = d.w + bb.y;
                } else {
                    *(float2*)&vh[r0 * HDIM + mc] = make_float2(d.x + bb.x, d.y + bb.y);
                    *(float2*)&vh[r1 * HDIM + mc] = make_float2(d.z + bb.x, d.w + bb.y);
                }
            }
        }
        __syncthreads();

        // ===== scores (fp32x2): att = q.k^T / sqrt(d) =====
        {
            const int i0 = (t >> 4) << 2;
            const int j0 = (t & 15) << 2;
            u64 a[4][2];
#pragma unroll
            for (int r = 0; r < 4; r++) { a[r][0] = 0ull; a[r][1] = 0ull; }
#pragma unroll
            for (int kk = 0; kk < HDIM; kk += 4) {
                ulonglong2 k0 = *(const ulonglong2*)&kt[(kk+0)*64 + j0];
                ulonglong2 k1 = *(const ulonglong2*)&kt[(kk+1)*64 + j0];
                ulonglong2 k2 = *(const ulonglong2*)&kt[(kk+2)*64 + j0];
                ulonglong2 k3 = *(const ulonglong2*)&kt[(kk+3)*64 + j0];
                float4 q0 = *(const float4*)&qh[(i0+0)*QS + kk];
                float4 q1 = *(const float4*)&qh[(i0+1)*QS + kk];
                float4 q2 = *(const float4*)&qh[(i0+2)*QS + kk];
                float4 q3 = *(const float4*)&qh[(i0+3)*QS + kk];
#pragma unroll
                for (int r = 0; r < 4; r++) {
                    float4 qr = (r==0) ? q0 : (r==1) ? q1 : (r==2) ? q2 : q3;
                    u64 d;
                    d = dup2(qr.x); ffma2(a[r][0], d, k0.x); ffma2(a[r][1], d, k0.y);
                    d = dup2(qr.y); ffma2(a[r][0], d, k1.x); ffma2(a[r][1], d, k1.y);
                    d = dup2(qr.z); ffma2(a[r][0], d, k2.x); ffma2(a[r][1], d, k2.y);
                    d = dup2(qr.w); ffma2(a[r][0], d, k3.x); ffma2(a[r][1], d, k3.y);
                }
            }
#pragma unroll
            for (int r = 0; r < 4; r++) {
                float2 lo = unpk(a[r][0]);
                float2 hi = unpk(a[r][1]);
                *(float4*)&att[(i0+r)*ATS + j0] = make_float4(
                    lo.x*inv_sqrt_d, lo.y*inv_sqrt_d, hi.x*inv_sqrt_d, hi.y*inv_sqrt_d);
            }
        }
        __syncthreads();

        // ---- softmax: 2 threads per row ----
        if (t < 128) {
            const int row = t >> 1;
            const int hf  = (t & 1) << 5;
            float* rp = att + row * ATS + hf;
            float m = rp[0];
#pragma unroll
            for (int j = 1; j < 32; j++) m = fmaxf(m, rp[j]);
            m = fmaxf(m, __shfl_xor_sync(0xFFFFFFFF, m, 1));
            float s = 0.f;
#pragma unroll
            for (int j = 0; j < 32; j++) { float e = __expf(rp[j] - m); rp[j] = e; s += e; }
            s += __shfl_xor_sync(0xFFFFFFFF, s, 1);
            float inv = 1.f / s;
#pragma unroll
            for (int j = 0; j < 32; j++) rp[j] *= inv;
        }
        __syncthreads();

        // ===== z = att @ vh -> kt as tf32 A-fragments (conflict-free) =====
        if (t < 128) {
            const int ks4  = t & 3;
            const int grps = (t >> 2) & 7;
            const int rmts = t >> 5;
            const int r0 = rmts * 16 + grps, r1 = r0 + 8;
            const int c8 = ks4 * 8;
            u64 a0[4] = {0ull,0ull,0ull,0ull};
            u64 a1[4] = {0ull,0ull,0ull,0ull};
#pragma unroll 4
            for (int j = 0; j < NFEAT; j += 2) {
                float2 p0 = *(const float2*)&att[r0 * ATS + j];
                float2 p1 = *(const float2*)&att[r1 * ATS + j];
#pragma unroll
                for (int jj = 0; jj < 2; jj++) {
                    ulonglong2 vA = *(const ulonglong2*)&vh[(j+jj)*HDIM + c8];
                    ulonglong2 vB = *(const ulonglong2*)&vh[(j+jj)*HDIM + c8 + 4];
                    u64 d0 = dup2(jj ? p0.y : p0.x);
                    u64 d1 = dup2(jj ? p1.y : p1.x);
                    ffma2(a0[0], d0, vA.x); ffma2(a0[1], d0, vA.y);
                    ffma2(a0[2], d0, vB.x); ffma2(a0[3], d0, vB.y);
                    ffma2(a1[0], d1, vA.x); ffma2(a1[1], d1, vA.y);
                    ffma2(a1[2], d1, vB.x); ffma2(a1[3], d1, vB.y);
                }
            }
            float z0[8], z1[8];
#pragma unroll
            for (int q = 0; q < 4; q++) {
                float2 f0 = unpk(a0[q]); z0[2*q] = f0.x; z0[2*q+1] = f0.y;
                float2 f1 = unpk(a1[q]); z1[2*q] = f1.x; z1[2*q+1] = f1.y;
            }
            const uint32_t base = (rmts * 4 + ks4) * 128 + grps * 16;
#pragma unroll
            for (int i = 0; i < 4; i++) {
                uint4 val = make_uint4(f2tf(z0[i]), f2tf(z1[i]),
                                       f2tf(z0[i+4]), f2tf(z1[i+4]));
                *(uint4*)&kt_u[base + ((i ^ ks4) << 2)] = val;
            }
        }
        __syncthreads();   // z frags visible; att/qh/vh dead -> staging ok

        // ===== stage W1 slice (both nc) via cp.async, then compute =====
        {
            const uint4* src = w1f4 + h * 2048;
#pragma unroll
            for (int j = 0; j < 4; j++) {       // nc0 -> WB0
                int idx = t + j * 256;
                CPA16(smu + ((WB0 + idx * 4) << 2), src + idx);
            }
#pragma unroll
            for (int j = 0; j < 4; j++) {       // nc1 -> WB1
                int idx = t + j * 256;
                CPA16(smu + ((WB1 + idx * 4) << 2), src + 1024 + idx);
            }
            CPCOMMIT();
            CPWAIT0();
            __syncthreads();
        }
        {
#pragma unroll
            for (int nc = 0; nc < 2; nc++) {
                const uint32_t* bw = smw + (nc ? WB1 : WB0);
#pragma unroll
                for (int ks = 0; ks < 4; ks++) {
                    uint4 za = *(const uint4*)&kt_u[(mt * 4 + ks) * 128 + grp * 16
                                                    + ((tig ^ ks) << 2)];
                    const uint32_t* bp = bw + (((ks * 16 + half * 8) * 32 + lane) << 1);
#pragma unroll
                    for (int nt = 0; nt < 8; nt++) {
                        uint2 bb = *(const uint2*)(bp + nt * 64);
                        mma_tf32(facc4[nc * 8 + nt], za.x, za.y, za.z, za.w, bb.x, bb.y);
                    }
                }
            }
        }
        // loop-top sync protects stage region + kt reuse
    }

    // ===== epilogue: f = relu(facc + b1 + x); dot W2 (x exact from gmem) ====
    {
        const int r0 = mt * 16 + grp, r1 = r0 + 8;
        float part = 0.f;
#pragma unroll
        for (int fi = 0; fi < 16; fi++) {
            int nc = fi >> 3, nt = fi & 7;
            int n  = nc * 128 + half * 64 + nt * 8 + 2 * tig;
            float2 b1v = *(const float2*)&b1[n];
            float2 x0  = *(const float2*)&xg[r0 * DIM + n];
            float2 x1  = *(const float2*)&xg[r1 * DIM + n];
            float2 w20 = *(const float2*)&W2[r0 * DIM + n];
            float2 w21 = *(const float2*)&W2[r1 * DIM + n];
            float4 d = facc4[fi];
            float f0 = fmaxf(d.x + b1v.x + x0.x, 0.f);
            float f1 = fmaxf(d.y + b1v.y + x0.y, 0.f);
            float f2 = fmaxf(d.z + b1v.x + x1.x, 0.f);
            float f3 = fmaxf(d.w + b1v.y + x1.y, 0.f);
            part += f0 * w20.x + f1 * w20.y + f2 * w21.x + f3 * w21.y;
        }
        red[t] = part;
    }
    __syncthreads();

#pragma unroll
    for (int s = 128; s > 0; s >>= 1) {
        if (t < s) red[t] += red[t + s];
        __syncthreads();
    }
    if (t == 0) {
        out[b] = 1.f / (1.f + __expf(-(red[0] + b2[0])));
    }
}

extern "C" void kernel_launch(void* const* d_in, const int* in_sizes, int n_in,
                              void* d_out, int out_size)
{
    const float* x  = (const float*)d_in[0];
    const float* Wq = (const float*)d_in[1];
    const float* bq = (const float*)d_in[2];
    const float* Wk = (const float*)d_in[3];
    const float* bk = (const float*)d_in[4];
    const float* Wv = (const float*)d_in[5];
    const float* bv = (const float*)d_in[6];
    const float* W1 = (const float*)d_in[7];
    const float* b1 = (const float*)d_in[8];
    const float* W2 = (const float*)d_in[9];
    const float* b2 = (const float*)d_in[10];
    float* out = (float*)d_out;

    prep_kernel<<<512, 256>>>(Wq, Wk, Wv, W1);

    const int smem_bytes = SMEM_FLOATS * (int)sizeof(float); // 109,568 B -> 2 CTAs/SM
    cudaFuncSetAttribute(autoint_kernel,
                         cudaFuncAttributeMaxDynamicSharedMemorySize, smem_bytes);
    autoint_kernel<<<8192, 256, smem_bytes>>>(x, bq, bk, bv, b1, W2, b2, out);
}

// round 11
// speedup vs baseline: 1.6541x; 1.2282x over previous
#include <cuda_runtime.h>
#include <math.h>
#include <stdint.h>

#define NFEAT 64
#define DIM   256
#define NHEAD 8
#define HDIM  32

// smem word layout (27392 words = 109,568 B -> 2 CTAs/SM):
//  axf  0..16384      x as tf32 A-fragments (persistent)
//  region 16384..27136 time-multiplexed:
//    proj staging SB0/SB1/SB2 (3 x 3072)           [proj phase]
//    Qf 16384 / Kf 18432 / Vf 20480 (3 x 2048)     [scatter..z]
//    WA 22528 (4096, W1 nc0), WB 16384 (4096, nc1) [W1 phase]
//  red 27136..27392 (epilogue)
#define QF_OFF 16384
#define KF_OFF 18432
#define VF_OFF 20480
#define SB0    16384
#define SB1    19456
#define SB2    22528
#define WA_OFF 22528
#define WB_OFF 16384
#define OFF_RED 27136
#define SMEM_FLOATS 27392

// pre-converted tf32 weight fragments (written by prep_kernel each launch)
// WPF: [h 8][ch 8][ks2 4][nt 12][lane 32][2]
// W1F: [h 8][nc 2][ks 4][nt 16][lane 32][2]
__device__ uint32_t WPF[8*8*4*12*32*2];
__device__ uint32_t W1F[8*2*4*16*32*2];

__device__ __forceinline__ uint32_t f2tf(float x) {
    uint32_t r; asm("cvt.rna.tf32.f32 %0, %1;" : "=r"(r) : "f"(x)); return r;
}
__device__ __forceinline__ void mma_tf32(float4& d,
    uint32_t a0, uint32_t a1, uint32_t a2, uint32_t a3,
    uint32_t b0, uint32_t b1)
{
    asm("mma.sync.aligned.m16n8k8.row.col.f32.tf32.tf32.f32 "
        "{%0,%1,%2,%3}, {%4,%5,%6,%7}, {%8,%9}, {%0,%1,%2,%3};"
        : "+f"(d.x), "+f"(d.y), "+f"(d.z), "+f"(d.w)
        : "r"(a0), "r"(a1), "r"(a2), "r"(a3), "r"(b0), "r"(b1));
}
__device__ __forceinline__ uint32_t s2u(const void* p) {
    uint32_t a;
    asm("{ .reg .u64 t; cvta.to.shared.u64 t, %1; cvt.u32.u64 %0, t; }"
        : "=r"(a) : "l"(p));
    return a;
}
#define CPA16(dst, src) \
    asm volatile("cp.async.cg.shared.global [%0], [%1], 16;" :: "r"(dst), "l"(src))
#define CPCOMMIT() asm volatile("cp.async.commit_group;" ::: "memory")
#define CPWAIT1()  asm volatile("cp.async.wait_group 1;"  ::: "memory")
#define CPWAIT0()  asm volatile("cp.async.wait_group 0;"  ::: "memory")

// D-fragment (cols 2tig,2tig+1) -> A-fragment (cols tig, tig+4) quad transpose.
// o0=(r0,c+tig) o1=(r1,c+tig) o2=(r0,c+tig+4) o3=(r1,c+tig+4)
__device__ __forceinline__ void quad_xpose(float4 d, int lane, int tig,
        float& o0, float& o1, float& o2, float& o3)
{
    int srcA = (lane & ~3) | (tig >> 1);
    int srcB = srcA + 2;
    float xA = __shfl_sync(0xFFFFFFFFu, d.x, srcA);
    float yA = __shfl_sync(0xFFFFFFFFu, d.y, srcA);
    float zA = __shfl_sync(0xFFFFFFFFu, d.z, srcA);
    float wA = __shfl_sync(0xFFFFFFFFu, d.w, srcA);
    float xB = __shfl_sync(0xFFFFFFFFu, d.x, srcB);
    float yB = __shfl_sync(0xFFFFFFFFu, d.y, srcB);
    float zB = __shfl_sync(0xFFFFFFFFu, d.z, srcB);
    float wB = __shfl_sync(0xFFFFFFFFu, d.w, srcB);
    bool odd = (tig & 1);
    o0 = odd ? yA : xA;
    o1 = odd ? wA : zA;
    o2 = odd ? yB : xB;
    o3 = odd ? wB : zB;
}

// B-fragment word index helpers (relative to Kf/Vf bases, uint32 units)
#define KF_W(j,kk) (((((kk)>>3)*8 + ((j)>>3))*32 + ((j)&7)*4 + ((kk)&3))*2 + (((kk)>>2)&1))
#define VF_W(j,dd) (((((j)>>3)*4 + ((dd)>>3))*32 + ((dd)&7)*4 + ((j)&3))*2 + (((j)>>2)&1))

// ---------------- prep: weights -> tf32 B-fragment order -----------------
__global__ __launch_bounds__(256)
void prep_kernel(const float* __restrict__ Wq, const float* __restrict__ Wk,
                 const float* __restrict__ Wv, const float* __restrict__ W1)
{
    int id = blockIdx.x * 256 + threadIdx.x;
    if (id < 98304) {                          // proj: 8*8*4*12*32
        int lane = id & 31;
        int g    = id >> 5;
        int nt   = g % 12;
        int ks2  = (g / 12) & 3;
        int ch   = (g / 48) & 7;
        int h    = g / 384;
        int mat  = nt >> 2;
        const float* W = (mat == 0) ? Wq : (mat == 1) ? Wk : Wv;
        int n = h * HDIM + (nt & 3) * 8 + (lane >> 2);
        int k = ch * 32 + ks2 * 8 + (lane & 3);
        uint2 v = make_uint2(f2tf(W[k * DIM + n]), f2tf(W[(k + 4) * DIM + n]));
        *(uint2*)&WPF[id * 2] = v;
    } else {                                   // W1: 8*2*4*16*32
        int j    = id - 98304;
        int lane = j & 31;
        int g    = j >> 5;
        int nt   = g % 16;
        int ks   = (g / 16) & 3;
        int nc   = (g / 64) & 1;
        int h    = g / 128;
        int n = nc * 128 + nt * 8 + (lane >> 2);
        int k = h * HDIM + ks * 8 + (lane & 3);
        uint2 v = make_uint2(f2tf(W1[k * DIM + n]), f2tf(W1[(k + 4) * DIM + n]));
        *(uint2*)&W1F[j * 2] = v;
    }
}

// ---------------- main ----------------
__global__ __launch_bounds__(256, 2)
void autoint_kernel(const float* __restrict__ x,
                    const float* __restrict__ bq, const float* __restrict__ bk,
                    const float* __restrict__ bv, const float* __restrict__ b1,
                    const float* __restrict__ W2, const float* __restrict__ b2,
                    float* __restrict__ out)
{
    extern __shared__ float sm[];
    uint32_t* smw   = (uint32_t*)sm;
    uint32_t* axf_u = smw;
    float* red = sm + OFF_RED;
    const uint32_t smu = s2u(sm);

    const int t = threadIdx.x;
    const int b = blockIdx.x;
    const float* xg = x + (size_t)b * (NFEAT * DIM);

    const int lane = t & 31;
    const int grp  = lane >> 2;
    const int tig  = lane & 3;
    const int w    = t >> 5;
    const int mt   = w & 3;
    const int half = w >> 2;
    const float isd = 0.17677669529663687f;   // 1/sqrt(32)

    // ---- phase 0: x -> tf32 A-fragment order ----
    {
        const float4* xg4 = (const float4*)xg;
#pragma unroll
        for (int n = t; n < NFEAT * DIM / 4; n += 256) {
            float4 v = xg4[n];
            int r   = n >> 6;
            int c4  = (n & 63) << 2;
            int rmt = r >> 4, rgr = r & 7, hi8 = (r >> 3) & 1;
            int ks  = c4 >> 3, chi = (c4 >> 2) & 1;
            uint32_t* d = axf_u + (((rmt * 32 + ks) * 32 + rgr * 4) << 2)
                          + hi8 + (chi << 1);
            d[0] = f2tf(v.x); d[4] = f2tf(v.y); d[8] = f2tf(v.z); d[12] = f2tf(v.w);
        }
    }

    float4 facc4[16];
#pragma unroll
    for (int i = 0; i < 16; i++) facc4[i] = make_float4(0.f, 0.f, 0.f, 0.f);

    const uint4* wpf4 = (const uint4*)WPF;   // 768 uint4 per (h,ch)
    const uint4* w1f4 = (const uint4*)W1F;   // 2048 uint4 per h

    for (int h = 0; h < NHEAD; h++) {
        const int hd = h * HDIM;
        __syncthreads();   // staging/frag region free; axf visible (h=0)

        // ===== QKV projection: staged B fragments, triple-buffered cp.async
        const int sbuf[3] = {SB0, SB1, SB2};
#pragma unroll
        for (int c = 0; c < 2; c++) {
            const uint4* src = wpf4 + (h * 8 + c) * 768;
#pragma unroll
            for (int j = 0; j < 3; j++) {
                int idx = t + j * 256;
                CPA16(smu + ((sbuf[c] + idx * 4) << 2), src + idx);
            }
            CPCOMMIT();
        }

        float4 D[6];
#pragma unroll
        for (int i = 0; i < 6; i++) D[i] = make_float4(0.f, 0.f, 0.f, 0.f);

        for (int ch = 0; ch < 8; ch++) {
            CPWAIT1();
            __syncthreads();
            if (ch + 2 < 8) {
                const uint4* src = wpf4 + (h * 8 + ch + 2) * 768;
                const int bofs = sbuf[(ch + 2) % 3];
#pragma unroll
                for (int j = 0; j < 3; j++) {
                    int idx = t + j * 256;
                    CPA16(smu + ((bofs + idx * 4) << 2), src + idx);
                }
            }
            CPCOMMIT();
            const uint32_t* bw = smw + sbuf[ch % 3];
#pragma unroll
            for (int ks2 = 0; ks2 < 4; ks2++) {
                uint4 av = *(const uint4*)&axf_u[((mt * 32 + ch * 4 + ks2) * 32 + lane) << 2];
                const uint32_t* bp = bw + (((ks2 * 12 + half * 6) * 32 + lane) << 1);
#pragma unroll
                for (int nt = 0; nt < 6; nt++) {
                    uint2 bb = *(const uint2*)(bp + nt * 64);
                    mma_tf32(D[nt], av.x, av.y, av.z, av.w, bb.x, bb.y);
                }
            }
        }
        __syncthreads();   // all proj reads done -> frag region writable

        // ===== scatter: q -> A-frags (scaled), k/v -> B-frags; issue W1 nc0
        {
            const int j0 = mt * 16 + grp, j1 = j0 + 8;
            if (half == 0) {
#pragma unroll
                for (int ks = 0; ks < 4; ks++) {       // q cols ks*8+2tig
                    float4 d = D[ks];
                    int n = ks * 8 + 2 * tig;
                    float2 bb = *(const float2*)&bq[hd + n];
                    d.x = (d.x + bb.x) * isd; d.y = (d.y + bb.y) * isd;
                    d.z = (d.z + bb.x) * isd; d.w = (d.w + bb.y) * isd;
                    float o0, o1, o2, o3;
                    quad_xpose(d, lane, tig, o0, o1, o2, o3);
                    ((uint4*)(smw + QF_OFF))[(mt * 4 + ks) * 32 + lane] =
                        make_uint4(f2tf(o0), f2tf(o1), f2tf(o2), f2tf(o3));
                }
                uint32_t* kf = smw + KF_OFF;
#pragma unroll
                for (int nt = 4; nt < 6; nt++) {       // k cols 0..15
                    float4 d = D[nt];
                    int kk = (nt - 4) * 8 + 2 * tig;
                    float2 bb = *(const float2*)&bk[hd + kk];
                    kf[KF_W(j0, kk)]     = f2tf(d.x + bb.x);
                    kf[KF_W(j0, kk + 1)] = f2tf(d.y + bb.y);
                    kf[KF_W(j1, kk)]     = f2tf(d.z + bb.x);
                    kf[KF_W(j1, kk + 1)] = f2tf(d.w + bb.y);
                }
            } else {
                uint32_t* kf = smw + KF_OFF;
#pragma unroll
                for (int nt = 0; nt < 2; nt++) {       // k cols 16..31
                    float4 d = D[nt];
                    int kk = 16 + nt * 8 + 2 * tig;
                    float2 bb = *(const float2*)&bk[hd + kk];
                    kf[KF_W(j0, kk)]     = f2tf(d.x + bb.x);
                    kf[KF_W(j0, kk + 1)] = f2tf(d.y + bb.y);
                    kf[KF_W(j1, kk)]     = f2tf(d.z + bb.x);
                    kf[KF_W(j1, kk + 1)] = f2tf(d.w + bb.y);
                }
                uint32_t* vf = smw + VF_OFF;
#pragma unroll
                for (int nt = 2; nt < 6; nt++) {       // v cols 0..31
                    float4 d = D[nt];
                    int dd = (nt - 2) * 8 + 2 * tig;
                    float2 bb = *(const float2*)&bv[hd + dd];
                    vf[VF_W(j0, dd)]     = f2tf(d.x + bb.x);
                    vf[VF_W(j0, dd + 1)] = f2tf(d.y + bb.y);
                    vf[VF_W(j1, dd)]     = f2tf(d.z + bb.x);
                    vf[VF_W(j1, dd + 1)] = f2tf(d.w + bb.y);
                }
            }
            // stage W1 nc0 into WA (dead SB2 region)
            const uint4* src = w1f4 + h * 2048;
#pragma unroll
            for (int j = 0; j < 4; j++) {
                int idx = t + j * 256;
                CPA16(smu + ((WA_OFF + idx * 4) << 2), src + idx);
            }
            CPCOMMIT();
        }
        __syncthreads();   // Qf/Kf/Vf visible

        // ===== scores mma: Ds = q @ k^T (already scaled by 1/sqrt(d))
        float4 Ds[8];
#pragma unroll
        for (int i = 0; i < 8; i++) Ds[i] = make_float4(0.f, 0.f, 0.f, 0.f);
#pragma unroll
        for (int ks = 0; ks < 4; ks++) {
            uint4 qa = ((const uint4*)(smw + QF_OFF))[(mt * 4 + ks) * 32 + lane];
#pragma unroll
            for (int nt = 0; nt < 8; nt++) {
                uint2 kb = ((const uint2*)(smw + KF_OFF))[(ks * 8 + nt) * 32 + lane];
                mma_tf32(Ds[nt], qa.x, qa.y, qa.z, qa.w, kb.x, kb.y);
            }
        }

        // ===== softmax fully in registers (rows r0=grp, r1=grp+8 of tile)
        float m0 = Ds[0].x, m1 = Ds[0].z;
#pragma unroll
        for (int nt = 0; nt < 8; nt++) {
            m0 = fmaxf(m0, fmaxf(Ds[nt].x, Ds[nt].y));
            m1 = fmaxf(m1, fmaxf(Ds[nt].z, Ds[nt].w));
        }
        m0 = fmaxf(m0, __shfl_xor_sync(0xFFFFFFFFu, m0, 1));
        m0 = fmaxf(m0, __shfl_xor_sync(0xFFFFFFFFu, m0, 2));
        m1 = fmaxf(m1, __shfl_xor_sync(0xFFFFFFFFu, m1, 1));
        m1 = fmaxf(m1, __shfl_xor_sync(0xFFFFFFFFu, m1, 2));
        float s0 = 0.f, s1 = 0.f;
#pragma unroll
        for (int nt = 0; nt < 8; nt++) {
            Ds[nt].x = __expf(Ds[nt].x - m0);
            Ds[nt].y = __expf(Ds[nt].y - m0);
            Ds[nt].z = __expf(Ds[nt].z - m1);
            Ds[nt].w = __expf(Ds[nt].w - m1);
            s0 += Ds[nt].x + Ds[nt].y;
            s1 += Ds[nt].z + Ds[nt].w;
        }
        s0 += __shfl_xor_sync(0xFFFFFFFFu, s0, 1);
        s0 += __shfl_xor_sync(0xFFFFFFFFu, s0, 2);
        s1 += __shfl_xor_sync(0xFFFFFFFFu, s1, 1);
        s1 += __shfl_xor_sync(0xFFFFFFFFu, s1, 2);
        const float inv0 = 1.f / s0, inv1 = 1.f / s1;

        __syncthreads();   // Qf/Kf dead -> WB writable
        {   // stage W1 nc1 into WB (dead Qf/Kf region)
            const uint4* src = w1f4 + h * 2048 + 1024;
#pragma unroll
            for (int j = 0; j < 4; j++) {
                int idx = t + j * 256;
                CPA16(smu + ((WB_OFF + idx * 4) << 2), src + idx);
            }
            CPCOMMIT();
        }

        // ===== z mma: Dz = e @ v (unnormalized; 1/s folded in below)
        float4 Dz[4];
#pragma unroll
        for (int i = 0; i < 4; i++) Dz[i] = make_float4(0.f, 0.f, 0.f, 0.f);
#pragma unroll
        for (int ksj = 0; ksj < 8; ksj++) {
            float o0, o1, o2, o3;
            quad_xpose(Ds[ksj], lane, tig, o0, o1, o2, o3);
            uint32_t a0 = f2tf(o0), a1 = f2tf(o1), a2 = f2tf(o2), a3 = f2tf(o3);
#pragma unroll
            for (int ntd = 0; ntd < 4; ntd++) {
                uint2 vb = ((const uint2*)(smw + VF_OFF))[(ksj * 4 + ntd) * 32 + lane];
                mma_tf32(Dz[ntd], a0, a1, a2, a3, vb.x, vb.y);
            }
        }
        // z D-frags -> W1 A-frags (normalize rows here)
        uint4 za4[4];
#pragma unroll
        for (int ks = 0; ks < 4; ks++) {
            float o0, o1, o2, o3;
            quad_xpose(Dz[ks], lane, tig, o0, o1, o2, o3);
            za4[ks] = make_uint4(f2tf(o0 * inv0), f2tf(o1 * inv1),
                                 f2tf(o2 * inv0), f2tf(o3 * inv1));
        }

        // ===== facc += z @ W1 : nc0 from WA, nc1 from WB
        CPWAIT1();
        __syncthreads();   // WA visible to all
        {
            const uint32_t* bw = smw + WA_OFF;
#pragma unroll
            for (int ks = 0; ks < 4; ks++) {
                uint4 za = za4[ks];
                const uint32_t* bp = bw + (((ks * 16 + half * 8) * 32 + lane) << 1);
#pragma unroll
                for (int nt = 0; nt < 8; nt++) {
                    uint2 bb = *(const uint2*)(bp + nt * 64);
                    mma_tf32(facc4[nt], za.x, za.y, za.z, za.w, bb.x, bb.y);
                }
            }
        }
        CPWAIT0();
        __syncthreads();   // WB visible to all
        {
            const uint32_t* bw = smw + WB_OFF;
#pragma unroll
            for (int ks = 0; ks < 4; ks++) {
                uint4 za = za4[ks];
                const uint32_t* bp = bw + (((ks * 16 + half * 8) * 32 + lane) << 1);
#pragma unroll
                for (int nt = 0; nt < 8; nt++) {
                    uint2 bb = *(const uint2*)(bp + nt * 64);
                    mma_tf32(facc4[8 + nt], za.x, za.y, za.z, za.w, bb.x, bb.y);
                }
            }
        }
        // loop-top sync protects region reuse
    }

    // ===== epilogue: f = relu(facc + b1 + x); dot W2 (x exact from gmem) ====
    {
        const int r0 = mt * 16 + grp, r1 = r0 + 8;
        float part = 0.f;
#pragma unroll
        for (int fi = 0; fi < 16; fi++) {
            int nc = fi >> 3, nt = fi & 7;
            int n  = nc * 128 + half * 64 + nt * 8 + 2 * tig;
            float2 b1v = *(const float2*)&b1[n];
            float2 x0  = *(const float2*)&xg[r0 * DIM + n];
            float2 x1  = *(const float2*)&xg[r1 * DIM + n];
            float2 w20 = *(const float2*)&W2[r0 * DIM + n];
            float2 w21 = *(const float2*)&W2[r1 * DIM + n];
            float4 d = facc4[fi];
            float f0 = fmaxf(d.x + b1v.x + x0.x, 0.f);
            float f1 = fmaxf(d.y + b1v.y + x0.y, 0.f);
            float f2 = fmaxf(d.z + b1v.x + x1.x, 0.f);
            float f3 = fmaxf(d.w + b1v.y + x1.y, 0.f);
            part += f0 * w20.x + f1 * w20.y + f2 * w21.x + f3 * w21.y;
        }
        red[t] = part;
    }
    __syncthreads();

#pragma unroll
    for (int s = 128; s > 0; s >>= 1) {
        if (t < s) red[t] += red[t + s];
        __syncthreads();
    }
    if (t == 0) {
        out[b] = 1.f / (1.f + __expf(-(red[0] + b2[0])));
    }
}

extern "C" void kernel_launch(void* const* d_in, const int* in_sizes, int n_in,
                              void* d_out, int out_size)
{
    const float* x  = (const float*)d_in[0];
    const float* Wq = (const float*)d_in[1];
    const float* bq = (const float*)d_in[2];
    const float* Wk = (const float*)d_in[3];
    const float* bk = (const float*)d_in[4];
    const float* Wv = (const float*)d_in[5];
    const float* bv = (const float*)d_in[6];
    const float* W1 = (const float*)d_in[7];
    const float* b1 = (const float*)d_in[8];
    const float* W2 = (const float*)d_in[9];
    const float* b2 = (const float*)d_in[10];
    float* out = (float*)d_out;

    prep_kernel<<<512, 256>>>(Wq, Wk, Wv, W1);

    const int smem_bytes = SMEM_FLOATS * (int)sizeof(float); // 109,568 B -> 2 CTAs/SM
    cudaFuncSetAttribute(autoint_kernel,
                         cudaFuncAttributeMaxDynamicSharedMemorySize, smem_bytes);
    autoint_kernel<<<8192, 256, smem_bytes>>>(x, bq, bk, bv, b1, W2, b2, out);
}

// round 12
// speedup vs baseline: 3.3468x; 2.0233x over previous
#include <cuda_runtime.h>
#include <math.h>
#include <stdint.h>

#define NFEAT 64
#define DIM   256
#define NHEAD 8
#define HDIM  32

// smem word offsets (u32 words). Total 17664 words = 70,656 B -> 2 CTAs/SM.
//  axf 0..8192                x as bf16 A-fragments (persistent)
//  proj staging SB0/1/2 (3 x 3072) in 8192..17408   [proj phase]
//  QF 8192 (1024) / KF 9216 (1024) / VF 10240 (1152)[scatter..z]
//  WA 11392 (2048) / WB 13440 (2048)                [W1 phase]
//  RED 17408..17664
#define SB0    8192
#define SB1    11264
#define SB2    14336
#define QF_OFF 8192
#define KF_OFF 9216
#define VF_OFF 10240
#define VF_S   36          // padded j2-stride (bank-conflict-free both sides)
#define WA_OFF 11392
#define WB_OFF 13440
#define OFF_RED 17408
#define SMEM_FLOATS 17664

// pre-converted bf16 weight B-fragments (written by prep_kernel each launch)
// WPF: [h 8][ks 16][nt 12][lane 32] uint2 {b0,b1}
// W1F: [h 8][nc 2][ks 2][nt 16][lane 32] uint2
__device__ __align__(16) uint32_t WPF[8*16*12*32*2];   // 98,304 words
__device__ __align__(16) uint32_t W1F[8*2*2*16*32*2];  // 32,768 words

// pack two fp32 -> bf16x2 (lo in low half)
__device__ __forceinline__ uint32_t pkbf(float lo, float hi) {
    uint32_t r;
    asm("cvt.rn.bf16x2.f32 %0, %1, %2;" : "=r"(r) : "f"(hi), "f"(lo));
    return r;
}
__device__ __forceinline__ void mma_bf16(float4& d,
    uint32_t a0, uint32_t a1, uint32_t a2, uint32_t a3,
    uint32_t b0, uint32_t b1)
{
    asm("mma.sync.aligned.m16n8k16.row.col.f32.bf16.bf16.f32 "
        "{%0,%1,%2,%3}, {%4,%5,%6,%7}, {%8,%9}, {%0,%1,%2,%3};"
        : "+f"(d.x), "+f"(d.y), "+f"(d.z), "+f"(d.w)
        : "r"(a0), "r"(a1), "r"(a2), "r"(a3), "r"(b0), "r"(b1));
}
__device__ __forceinline__ uint32_t s2u(const void* p) {
    uint32_t a;
    asm("{ .reg .u64 t; cvta.to.shared.u64 t, %1; cvt.u32.u64 %0, t; }"
        : "=r"(a) : "l"(p));
    return a;
}
#define CPA16(dst, src) \
    asm volatile("cp.async.cg.shared.global [%0], [%1], 16;" :: "r"(dst), "l"(src))
#define CPCOMMIT() asm volatile("cp.async.commit_group;" ::: "memory")
#define CPWAIT1()  asm volatile("cp.async.wait_group 1;"  ::: "memory")
#define CPWAIT0()  asm volatile("cp.async.wait_group 0;"  ::: "memory")

// ---------------- prep: weights -> bf16 B-fragment order -----------------
__global__ __launch_bounds__(256)
void prep_kernel(const float* __restrict__ Wq, const float* __restrict__ Wk,
                 const float* __restrict__ Wv, const float* __restrict__ W1)
{
    int id = blockIdx.x * 256 + threadIdx.x;   // 65536 total
    if (id < 49152) {                          // proj: 8h * 16ks * 12nt * 32lane
        int lane = id & 31;
        int g    = id >> 5;
        int nt   = g % 12;
        int ks   = (g / 12) & 15;
        int h    = g / 192;
        int mat  = nt >> 2;
        const float* W = (mat == 0) ? Wq : (mat == 1) ? Wk : Wv;
        int n  = h * HDIM + (nt & 3) * 8 + (lane >> 2);
        int k0 = ks * 16 + (lane & 3) * 2;
        uint2 v;
        v.x = pkbf(W[k0 * DIM + n],       W[(k0 + 1) * DIM + n]);
        v.y = pkbf(W[(k0 + 8) * DIM + n], W[(k0 + 9) * DIM + n]);
        *(uint2*)&WPF[id * 2] = v;
    } else {                                   // W1: 8h * 2nc * 2ks * 16nt * 32lane
        int j    = id - 49152;
        int lane = j & 31;
        int g    = j >> 5;
        int nt   = g % 16;
        int ks   = (g / 16) & 1;
        int nc   = (g / 32) & 1;
        int h    = g / 64;
        int n  = nc * 128 + nt * 8 + (lane >> 2);
        int k0 = h * HDIM + ks * 16 + (lane & 3) * 2;
        uint2 v;
        v.x = pkbf(W1[k0 * DIM + n],       W1[(k0 + 1) * DIM + n]);
        v.y = pkbf(W1[(k0 + 8) * DIM + n], W1[(k0 + 9) * DIM + n]);
        *(uint2*)&W1F[j * 2] = v;
    }
}

// ---------------- main ----------------
__global__ __launch_bounds__(256, 2)
void autoint_kernel(const float* __restrict__ x,
                    const float* __restrict__ bq, const float* __restrict__ bk,
                    const float* __restrict__ bv, const float* __restrict__ b1,
                    const float* __restrict__ W2, const float* __restrict__ b2,
                    float* __restrict__ out)
{
    extern __shared__ float sm[];
    uint32_t* smw = (uint32_t*)sm;
    float* red = sm + OFF_RED;
    const uint32_t smu = s2u(sm);

    const int t = threadIdx.x;
    const int b = blockIdx.x;
    const float* xg = x + (size_t)b * (NFEAT * DIM);

    const int lane = t & 31;
    const int grp  = lane >> 2;
    const int tig  = lane & 3;
    const int w    = t >> 5;
    const int mt   = w & 3;
    const int half = w >> 2;
    const float isd = 0.17677669529663687f;   // 1/sqrt(32)

    // ---- phase 0: x -> bf16 A-fragment order ----
    // axf: [mt 4][ks 16][lane 32] uint4 {a0,a1,a2,a3}
    {
        const float4* xg4 = (const float4*)xg;
#pragma unroll
        for (int n = t; n < NFEAT * DIM / 4; n += 256) {
            float4 v = xg4[n];
            int r   = n >> 6;
            int c4  = (n & 63) << 2;
            int rmt = r >> 4, rgr = r & 7, hi8 = (r >> 3) & 1;
            int ks  = c4 >> 4, koff = c4 & 15;
            int hi  = koff >> 3, tg0 = (koff >> 1) & 3;   // koff in {0,4,8,12}
            int comp = hi8 + (hi << 1);
            uint32_t* d = smw + (((rmt * 16 + ks) * 32 + rgr * 4) << 2) + comp;
            d[tg0 * 4]       = pkbf(v.x, v.y);
            d[(tg0 + 1) * 4] = pkbf(v.z, v.w);
        }
    }

    float4 facc4[16];
#pragma unroll
    for (int i = 0; i < 16; i++) facc4[i] = make_float4(0.f, 0.f, 0.f, 0.f);

    const uint4* wpf4 = (const uint4*)WPF;   // per (h): 3072 uint4; per chunk: 768
    const uint4* w1f4 = (const uint4*)W1F;   // per h: 1024 uint4

    for (int h = 0; h < NHEAD; h++) {
        const int hd = h * HDIM;
        __syncthreads();   // all prior-phase regions free; axf visible (h=0)

        // ===== QKV projection: 4 chunks of 4 ksteps, triple-buffered =====
        const int sbuf[3] = {SB0, SB1, SB2};
#pragma unroll
        for (int c = 0; c < 2; c++) {
            const uint4* src = wpf4 + h * 3072 + c * 768;
#pragma unroll
            for (int j = 0; j < 3; j++) {
                int idx = t + j * 256;
                CPA16(smu + ((sbuf[c] + idx * 4) << 2), src + idx);
            }
            CPCOMMIT();
        }

        float4 D[6];
#pragma unroll
        for (int i = 0; i < 6; i++) D[i] = make_float4(0.f, 0.f, 0.f, 0.f);

        for (int ch = 0; ch < 4; ch++) {
            CPWAIT1();
            __syncthreads();
            if (ch + 2 < 4) {
                const uint4* src = wpf4 + h * 3072 + (ch + 2) * 768;
                const int bofs = sbuf[(ch + 2) % 3];
#pragma unroll
                for (int j = 0; j < 3; j++) {
                    int idx = t + j * 256;
                    CPA16(smu + ((bofs + idx * 4) << 2), src + idx);
                }
            }
            CPCOMMIT();
            const uint32_t* bw = smw + sbuf[ch % 3];
#pragma unroll
            for (int ks2 = 0; ks2 < 4; ks2++) {
                int ks = ch * 4 + ks2;
                uint4 av = ((const uint4*)smw)[(mt * 16 + ks) * 32 + lane];
                const uint32_t* bp = bw + (((ks2 * 12 + half * 6) * 32 + lane) << 1);
#pragma unroll
                for (int nt = 0; nt < 6; nt++) {
                    uint2 bb = *(const uint2*)(bp + nt * 64);
                    mma_bf16(D[nt], av.x, av.y, av.z, av.w, bb.x, bb.y);
                }
            }
        }
        __syncthreads();   // proj reads done -> frag regions writable

        // ===== scatter q->A-frags, k/v->B-frags; stage W1 (both halves) ====
        if (half == 0) {
            // q: D[0..3], cols n = nt*8 + 2tig; pack straight to A-frags
#pragma unroll
            for (int ks = 0; ks < 2; ks++) {
                float4 dA = D[2 * ks];      // cols 16ks + 2tig
                float4 dB = D[2 * ks + 1];  // cols 16ks + 8 + 2tig
                float2 bA = *(const float2*)&bq[hd + ks * 16 + 2 * tig];
                float2 bB = *(const float2*)&bq[hd + ks * 16 + 8 + 2 * tig];
                uint4 qa;
                qa.x = pkbf((dA.x + bA.x) * isd, (dA.y + bA.y) * isd);
                qa.y = pkbf((dA.z + bA.x) * isd, (dA.w + bA.y) * isd);
                qa.z = pkbf((dB.x + bB.x) * isd, (dB.y + bB.y) * isd);
                qa.w = pkbf((dB.z + bB.x) * isd, (dB.w + bB.y) * isd);
                ((uint4*)(smw + QF_OFF))[(mt * 2 + ks) * 32 + lane] = qa;
            }
            // k lower: D[4] (kk 0..7, breg0), D[5] (kk 8..15, breg1); kst 0
#pragma unroll
            for (int nt = 4; nt < 6; nt++) {
                float4 d = D[nt];
                int base = (nt - 4) * 8;
                float2 bb = *(const float2*)&bk[hd + base + 2 * tig];
                int breg = (nt == 5);
                uint32_t* kf = smw + KF_OFF;
                int i0 = (((0 * 8 + mt * 2) * 32 + grp * 4 + tig) << 1) + breg;
                int i1 = (((0 * 8 + mt * 2 + 1) * 32 + grp * 4 + tig) << 1) + breg;
                kf[i0] = pkbf(d.x + bb.x, d.y + bb.y);
                kf[i1] = pkbf(d.z + bb.x, d.w + bb.y);
            }
        } else {
            // k upper: D[0] (kk 16..23, breg0), D[1] (kk 24..31, breg1); kst 1
#pragma unroll
            for (int nt = 0; nt < 2; nt++) {
                float4 d = D[nt];
                int base = 16 + nt * 8;
                float2 bb = *(const float2*)&bk[hd + base + 2 * tig];
                int breg = nt;
                uint32_t* kf = smw + KF_OFF;
                int i0 = (((1 * 8 + mt * 2) * 32 + grp * 4 + tig) << 1) + breg;
                int i1 = (((1 * 8 + mt * 2 + 1) * 32 + grp * 4 + tig) << 1) + breg;
                kf[i0] = pkbf(d.x + bb.x, d.y + bb.y);
                kf[i1] = pkbf(d.z + bb.x, d.w + bb.y);
            }
            // v: D[2..5], cols d0 = (nt-2)*8 + 2tig; pair rows via shfl^4
            uint32_t* vf = smw + VF_OFF;
#pragma unroll
            for (int nt = 2; nt < 6; nt++) {
                float4 d = D[nt];
                int d0 = (nt - 2) * 8 + 2 * tig;
                float2 bb = *(const float2*)&bv[hd + d0];
                float vx = d.x + bb.x, vy = d.y + bb.y;
                float vz = d.z + bb.x, vw = d.w + bb.y;
                float px = __shfl_xor_sync(0xFFFFFFFFu, vx, 4);
                float py = __shfl_xor_sync(0xFFFFFFFFu, vy, 4);
                float pz = __shfl_xor_sync(0xFFFFFFFFu, vz, 4);
                float pw = __shfl_xor_sync(0xFFFFFFFFu, vw, 4);
                if (!(grp & 1)) {
                    int r0  = mt * 16 + grp;
                    int j2a = r0 >> 1, j2b = j2a + 4;
                    vf[d0 * VF_S + j2a]       = pkbf(vx, px);
                    vf[(d0 + 1) * VF_S + j2a] = pkbf(vy, py);
                    vf[d0 * VF_S + j2b]       = pkbf(vz, pz);
                    vf[(d0 + 1) * VF_S + j2b] = pkbf(vw, pw);
                }
            }
        }
        // stage W1 both halves (WA=nc0, WB=nc1)
        {
            const uint4* src = w1f4 + h * 1024;
#pragma unroll
            for (int j = 0; j < 2; j++) {
                int idx = t + j * 256;
                CPA16(smu + ((WA_OFF + idx * 4) << 2), src + idx);
            }
#pragma unroll
            for (int j = 0; j < 2; j++) {
                int idx = t + j * 256;
                CPA16(smu + ((WB_OFF + idx * 4) << 2), src + 512 + idx);
            }
            CPCOMMIT();
        }
        __syncthreads();   // QF/KF/VF visible

        // ===== scores mma: Ds = q @ k^T (pre-scaled) =====
        float4 Ds[8];
#pragma unroll
        for (int i = 0; i < 8; i++) Ds[i] = make_float4(0.f, 0.f, 0.f, 0.f);
#pragma unroll
        for (int ks = 0; ks < 2; ks++) {
            uint4 qa = ((const uint4*)(smw + QF_OFF))[(mt * 2 + ks) * 32 + lane];
#pragma unroll
            for (int nt = 0; nt < 8; nt++) {
                uint2 kb = ((const uint2*)(smw + KF_OFF))[(ks * 8 + nt) * 32 + lane];
                mma_bf16(Ds[nt], qa.x, qa.y, qa.z, qa.w, kb.x, kb.y);
            }
        }

        // ===== softmax in registers (rows grp, grp+8 of tile mt) =====
        float m0 = Ds[0].x, m1 = Ds[0].z;
#pragma unroll
        for (int nt = 0; nt < 8; nt++) {
            m0 = fmaxf(m0, fmaxf(Ds[nt].x, Ds[nt].y));
            m1 = fmaxf(m1, fmaxf(Ds[nt].z, Ds[nt].w));
        }
        m0 = fmaxf(m0, __shfl_xor_sync(0xFFFFFFFFu, m0, 1));
        m0 = fmaxf(m0, __shfl_xor_sync(0xFFFFFFFFu, m0, 2));
        m1 = fmaxf(m1, __shfl_xor_sync(0xFFFFFFFFu, m1, 1));
        m1 = fmaxf(m1, __shfl_xor_sync(0xFFFFFFFFu, m1, 2));
        float s0 = 0.f, s1 = 0.f;
#pragma unroll
        for (int nt = 0; nt < 8; nt++) {
            Ds[nt].x = __expf(Ds[nt].x - m0);
            Ds[nt].y = __expf(Ds[nt].y - m0);
            Ds[nt].z = __expf(Ds[nt].z - m1);
            Ds[nt].w = __expf(Ds[nt].w - m1);
            s0 += Ds[nt].x + Ds[nt].y;
            s1 += Ds[nt].z + Ds[nt].w;
        }
        s0 += __shfl_xor_sync(0xFFFFFFFFu, s0, 1);
        s0 += __shfl_xor_sync(0xFFFFFFFFu, s0, 2);
        s1 += __shfl_xor_sync(0xFFFFFFFFu, s1, 1);
        s1 += __shfl_xor_sync(0xFFFFFFFFu, s1, 2);
        const float inv0 = 1.f / s0, inv1 = 1.f / s1;

        // ===== z mma: A straight from Ds (normalized), B from vf =====
        float4 Dz[4];
#pragma unroll
        for (int i = 0; i < 4; i++) Dz[i] = make_float4(0.f, 0.f, 0.f, 0.f);
        const uint32_t* vfw = smw + VF_OFF;
#pragma unroll
        for (int kz = 0; kz < 4; kz++) {
            uint32_t a0 = pkbf(Ds[2*kz].x   * inv0, Ds[2*kz].y   * inv0);
            uint32_t a1 = pkbf(Ds[2*kz].z   * inv1, Ds[2*kz].w   * inv1);
            uint32_t a2 = pkbf(Ds[2*kz+1].x * inv0, Ds[2*kz+1].y * inv0);
            uint32_t a3 = pkbf(Ds[2*kz+1].z * inv1, Ds[2*kz+1].w * inv1);
#pragma unroll
            for (int ntd = 0; ntd < 4; ntd++) {
                uint32_t b0 = vfw[(ntd * 8 + grp) * VF_S + 8 * kz + tig];
                uint32_t b1 = vfw[(ntd * 8 + grp) * VF_S + 8 * kz + tig + 4];
                mma_bf16(Dz[ntd], a0, a1, a2, a3, b0, b1);
            }
        }
        // z D-frags -> W1 A-frags (direct pack, no shuffle)
        uint4 za[2];
#pragma unroll
        for (int ks = 0; ks < 2; ks++) {
            za[ks].x = pkbf(Dz[2*ks].x,   Dz[2*ks].y);
            za[ks].y = pkbf(Dz[2*ks].z,   Dz[2*ks].w);
            za[ks].z = pkbf(Dz[2*ks+1].x, Dz[2*ks+1].y);
            za[ks].w = pkbf(Dz[2*ks+1].z, Dz[2*ks+1].w);
        }

        // ===== facc += z @ W1 =====
        CPWAIT0();
        __syncthreads();   // WA/WB visible to all
#pragma unroll
        for (int nc = 0; nc < 2; nc++) {
            const uint32_t* bw = smw + (nc ? WB_OFF : WA_OFF);
#pragma unroll
            for (int ks = 0; ks < 2; ks++) {
                const uint32_t* bp = bw + (((ks * 16 + half * 8) * 32 + lane) << 1);
#pragma unroll
                for (int nt = 0; nt < 8; nt++) {
                    uint2 bb = *(const uint2*)(bp + nt * 64);
                    mma_bf16(facc4[nc * 8 + nt], za[ks].x, za[ks].y, za[ks].z, za[ks].w,
                             bb.x, bb.y);
                }
            }
        }
        // loop-top sync protects region reuse
    }

    // ===== epilogue: f = relu(facc + b1 + x); dot W2 (x exact from gmem) ====
    {
        const int r0 = mt * 16 + grp, r1 = r0 + 8;
        float part = 0.f;
#pragma unroll
        for (int fi = 0; fi < 16; fi++) {
            int nc = fi >> 3, nt = fi & 7;
            int n  = nc * 128 + half * 64 + nt * 8 + 2 * tig;
            float2 b1v = *(const float2*)&b1[n];
            float2 x0  = *(const float2*)&xg[r0 * DIM + n];
            float2 x1  = *(const float2*)&xg[r1 * DIM + n];
            float2 w20 = *(const float2*)&W2[r0 * DIM + n];
            float2 w21 = *(const float2*)&W2[r1 * DIM + n];
            float4 d = facc4[fi];
            float f0 = fmaxf(d.x + b1v.x + x0.x, 0.f);
            float f1 = fmaxf(d.y + b1v.y + x0.y, 0.f);
            float f2 = fmaxf(d.z + b1v.x + x1.x, 0.f);
            float f3 = fmaxf(d.w + b1v.y + x1.y, 0.f);
            part += f0 * w20.x + f1 * w20.y + f2 * w21.x + f3 * w21.y;
        }
        red[t] = part;
    }
    __syncthreads();

#pragma unroll
    for (int s = 128; s > 0; s >>= 1) {
        if (t < s) red[t] += red[t + s];
        __syncthreads();
    }
    if (t == 0) {
        out[b] = 1.f / (1.f + __expf(-(red[0] + b2[0])));
    }
}

extern "C" void kernel_launch(void* const* d_in, const int* in_sizes, int n_in,
                              void* d_out, int out_size)
{
    const float* x  = (const float*)d_in[0];
    const float* Wq = (const float*)d_in[1];
    const float* bq = (const float*)d_in[2];
    const float* Wk = (const float*)d_in[3];
    const float* bk = (const float*)d_in[4];
    const float* Wv = (const float*)d_in[5];
    const float* bv = (const float*)d_in[6];
    const float* W1 = (const float*)d_in[7];
    const float* b1 = (const float*)d_in[8];
    const float* W2 = (const float*)d_in[9];
    const float* b2 = (const float*)d_in[10];
    float* out = (float*)d_out;

    prep_kernel<<<256, 256>>>(Wq, Wk, Wv, W1);

    const int smem_bytes = SMEM_FLOATS * (int)sizeof(float); // 70,656 B -> 2 CTAs/SM
    cudaFuncSetAttribute(autoint_kernel,
                         cudaFuncAttributeMaxDynamicSharedMemorySize, smem_bytes);
    autoint_kernel<<<8192, 256, smem_bytes>>>(x, bq, bk, bv, b1, W2, b2, out);
}

// round 13
// speedup vs baseline: 3.6744x; 1.0979x over previous
#include <cuda_runtime.h>
#include <math.h>
#include <stdint.h>

#define NFEAT 64
#define DIM   256
#define NHEAD 8
#define HDIM  32

// smem word offsets (u32 words). Total 20736 words = 82,944 B -> 2 CTAs/SM.
//  axf 0..8192                 x as bf16 A-fragments (persistent)
//  proj staging PA0 8192 (6144) / PA1 14336 (6144)   [proj phase]
//  QF 8192 / KF 9216 / VF 10240 / WA 11392 / ZA 15488 [scatter..W1]
//  RED 20480..20736
#define PA0    8192
#define PA1    14336
#define QF_OFF 8192
#define KF_OFF 9216
#define VF_OFF 10240
#define VF_S   36
#define WA_OFF 11392
#define ZA_OFF 15488
#define OFF_RED 20480
#define SMEM_FLOATS 20736

// bf16 weight B-fragments, nt-PAIRED as uint4 (prep_kernel each launch)
// WPF: [h 8][ks 16][p 6][lane 32] uint4 {ntA.b0, ntA.b1, ntB.b0, ntB.b1}
// W1F: [h 8][nc 2][ks 2][p 8][lane 32] uint4
__device__ __align__(16) uint32_t WPF[8*16*6*32*4];   // 98,304 words
__device__ __align__(16) uint32_t W1F[8*2*2*8*32*4];  // 32,768 words

__device__ __forceinline__ uint32_t pkbf(float lo, float hi) {
    uint32_t r;
    asm("cvt.rn.bf16x2.f32 %0, %1, %2;" : "=r"(r) : "f"(hi), "f"(lo));
    return r;
}
__device__ __forceinline__ void mma_bf16(float4& d,
    uint32_t a0, uint32_t a1, uint32_t a2, uint32_t a3,
    uint32_t b0, uint32_t b1)
{
    asm("mma.sync.aligned.m16n8k16.row.col.f32.bf16.bf16.f32 "
        "{%0,%1,%2,%3}, {%4,%5,%6,%7}, {%8,%9}, {%0,%1,%2,%3};"
        : "+f"(d.x), "+f"(d.y), "+f"(d.z), "+f"(d.w)
        : "r"(a0), "r"(a1), "r"(a2), "r"(a3), "r"(b0), "r"(b1));
}
__device__ __forceinline__ uint32_t s2u(const void* p) {
    uint32_t a;
    asm("{ .reg .u64 t; cvta.to.shared.u64 t, %1; cvt.u32.u64 %0, t; }"
        : "=r"(a) : "l"(p));
    return a;
}
#define CPA16(dst, src) \
    asm volatile("cp.async.cg.shared.global [%0], [%1], 16;" :: "r"(dst), "l"(src))
#define CPCOMMIT() asm volatile("cp.async.commit_group;" ::: "memory")
#define CPWAIT1()  asm volatile("cp.async.wait_group 1;"  ::: "memory")
#define CPWAIT0()  asm volatile("cp.async.wait_group 0;"  ::: "memory")

// ---------------- prep: weights -> paired bf16 B-fragments ----------------
__global__ __launch_bounds__(256)
void prep_kernel(const float* __restrict__ Wq, const float* __restrict__ Wk,
                 const float* __restrict__ Wv, const float* __restrict__ W1)
{
    int id = blockIdx.x * 256 + threadIdx.x;   // 32768 uint4 slots
    if (id < 24576) {                          // WPF: [h][ks][p][lane]
        int lane = id & 31;
        int g    = id >> 5;
        int p    = g % 6;
        int ks   = (g / 6) & 15;
        int h    = g / 96;
        uint4 v;
#pragma unroll
        for (int e = 0; e < 2; e++) {
            int nt  = 2 * p + e;
            int mat = nt >> 2;
            const float* W = (mat == 0) ? Wq : (mat == 1) ? Wk : Wv;
            int n  = h * HDIM + (nt & 3) * 8 + (lane >> 2);
            int k0 = ks * 16 + (lane & 3) * 2;
            uint32_t b0 = pkbf(W[k0 * DIM + n],       W[(k0 + 1) * DIM + n]);
            uint32_t b1 = pkbf(W[(k0 + 8) * DIM + n], W[(k0 + 9) * DIM + n]);
            if (e == 0) { v.x = b0; v.y = b1; } else { v.z = b0; v.w = b1; }
        }
        ((uint4*)WPF)[id] = v;
    } else {                                   // W1F: [h][nc][ks][p][lane]
        int j    = id - 24576;
        int lane = j & 31;
        int g    = j >> 5;
        int p    = g & 7;
        int ks   = (g >> 3) & 1;
        int nc   = (g >> 4) & 1;
        int h    = g >> 5;
        uint4 v;
#pragma unroll
        for (int e = 0; e < 2; e++) {
            int nt = 2 * p + e;                // 0..15
            int n  = nc * 128 + nt * 8 + (lane >> 2);
            int k0 = h * HDIM + ks * 16 + (lane & 3) * 2;
            uint32_t b0 = pkbf(W1[k0 * DIM + n],       W1[(k0 + 1) * DIM + n]);
            uint32_t b1 = pkbf(W1[(k0 + 8) * DIM + n], W1[(k0 + 9) * DIM + n]);
            if (e == 0) { v.x = b0; v.y = b1; } else { v.z = b0; v.w = b1; }
        }
        ((uint4*)W1F)[j] = v;
    }
}

// ---------------- main ----------------
__global__ __launch_bounds__(256, 2)
void autoint_kernel(const float* __restrict__ x,
                    const float* __restrict__ bq, const float* __restrict__ bk,
                    const float* __restrict__ bv, const float* __restrict__ b1,
                    const float* __restrict__ W2, const float* __restrict__ b2,
                    float* __restrict__ out)
{
    extern __shared__ float sm[];
    uint32_t* smw = (uint32_t*)sm;
    float* red = sm + OFF_RED;
    const uint32_t smu = s2u(sm);

    const int t = threadIdx.x;
    const int b = blockIdx.x;
    const float* xg = x + (size_t)b * (NFEAT * DIM);

    const int lane = t & 31;
    const int grp  = lane >> 2;
    const int tig  = lane & 3;
    const int w    = t >> 5;
    const int mt   = w & 3;
    const int half = w >> 2;
    const float isd = 0.17677669529663687f;   // 1/sqrt(32)

    // ---- phase 0: x -> bf16 A-fragment order ----
    {
        const float4* xg4 = (const float4*)xg;
#pragma unroll
        for (int n = t; n < NFEAT * DIM / 4; n += 256) {
            float4 v = xg4[n];
            int r   = n >> 6;
            int c4  = (n & 63) << 2;
            int rmt = r >> 4, rgr = r & 7, hi8 = (r >> 3) & 1;
            int ks  = c4 >> 4, koff = c4 & 15;
            int hi  = koff >> 3, tg0 = (koff >> 1) & 3;
            int comp = hi8 + (hi << 1);
            uint32_t* d = smw + (((rmt * 16 + ks) * 32 + rgr * 4) << 2) + comp;
            d[tg0 * 4]       = pkbf(v.x, v.y);
            d[(tg0 + 1) * 4] = pkbf(v.z, v.w);
        }
    }

    float4 facc4[16];
#pragma unroll
    for (int i = 0; i < 16; i++) facc4[i] = make_float4(0.f, 0.f, 0.f, 0.f);

    const uint4* wpf4 = (const uint4*)WPF;   // 3072 uint4 per h; 1536 per chunk
    const uint4* w1f4 = (const uint4*)W1F;   // 1024 uint4 per h

    for (int h = 0; h < NHEAD; h++) {
        const int hd = h * HDIM;
        __syncthreads();   // frag/staging regions free; axf visible (h=0)

        // ===== QKV projection: 2 chunks of 8 ksteps, double-buffered =====
#pragma unroll
        for (int c = 0; c < 2; c++) {
            const uint4* src = wpf4 + h * 3072 + c * 1536;
            const int bofs = c ? PA1 : PA0;
#pragma unroll
            for (int j = 0; j < 6; j++) {
                int idx = t + j * 256;
                CPA16(smu + ((bofs + idx * 4) << 2), src + idx);
            }
            CPCOMMIT();
        }

        float4 D[6];
#pragma unroll
        for (int i = 0; i < 6; i++) D[i] = make_float4(0.f, 0.f, 0.f, 0.f);

#pragma unroll
        for (int ch = 0; ch < 2; ch++) {
            if (ch == 0) { CPWAIT1(); } else { CPWAIT0(); }
            __syncthreads();
            const uint4* bw4 = (const uint4*)(smw + (ch ? PA1 : PA0));
#pragma unroll
            for (int ksl = 0; ksl < 8; ksl++) {
                int ks = ch * 8 + ksl;
                uint4 av = ((const uint4*)smw)[(mt * 16 + ks) * 32 + lane];
                const uint4* bp = bw4 + (ksl * 6 + half * 3) * 32 + lane;
#pragma unroll
                for (int j = 0; j < 3; j++) {
                    uint4 bb = bp[j * 32];
                    mma_bf16(D[2*j],   av.x, av.y, av.z, av.w, bb.x, bb.y);
                    mma_bf16(D[2*j+1], av.x, av.y, av.z, av.w, bb.z, bb.w);
                }
            }
        }
        __syncthreads();   // proj reads done -> frag regions writable

        // ===== scatter q->A-frags, k/v->B-frags; stage W1 (single region) ==
        if (half == 0) {
#pragma unroll
            for (int ks = 0; ks < 2; ks++) {
                float4 dA = D[2 * ks];
                float4 dB = D[2 * ks + 1];
                float2 bA = *(const float2*)&bq[hd + ks * 16 + 2 * tig];
                float2 bB = *(const float2*)&bq[hd + ks * 16 + 8 + 2 * tig];
                uint4 qa;
                qa.x = pkbf((dA.x + bA.x) * isd, (dA.y + bA.y) * isd);
                qa.y = pkbf((dA.z + bA.x) * isd, (dA.w + bA.y) * isd);
                qa.z = pkbf((dB.x + bB.x) * isd, (dB.y + bB.y) * isd);
                qa.w = pkbf((dB.z + bB.x) * isd, (dB.w + bB.y) * isd);
                ((uint4*)(smw + QF_OFF))[(mt * 2 + ks) * 32 + lane] = qa;
            }
#pragma unroll
            for (int nt = 4; nt < 6; nt++) {       // k cols 0..15
                float4 d = D[nt];
                int base = (nt - 4) * 8;
                float2 bb = *(const float2*)&bk[hd + base + 2 * tig];
                int breg = (nt == 5);
                uint32_t* kf = smw + KF_OFF;
                int i0 = (((0 * 8 + mt * 2) * 32 + grp * 4 + tig) << 1) + breg;
                int i1 = (((0 * 8 + mt * 2 + 1) * 32 + grp * 4 + tig) << 1) + breg;
                kf[i0] = pkbf(d.x + bb.x, d.y + bb.y);
                kf[i1] = pkbf(d.z + bb.x, d.w + bb.y);
            }
        } else {
#pragma unroll
            for (int nt = 0; nt < 2; nt++) {       // k cols 16..31
                float4 d = D[nt];
                int base = 16 + nt * 8;
                float2 bb = *(const float2*)&bk[hd + base + 2 * tig];
                int breg = nt;
                uint32_t* kf = smw + KF_OFF;
                int i0 = (((1 * 8 + mt * 2) * 32 + grp * 4 + tig) << 1) + breg;
                int i1 = (((1 * 8 + mt * 2 + 1) * 32 + grp * 4 + tig) << 1) + breg;
                kf[i0] = pkbf(d.x + bb.x, d.y + bb.y);
                kf[i1] = pkbf(d.z + bb.x, d.w + bb.y);
            }
            uint32_t* vf = smw + VF_OFF;
#pragma unroll
            for (int nt = 2; nt < 6; nt++) {       // v cols 0..31
                float4 d = D[nt];
                int d0 = (nt - 2) * 8 + 2 * tig;
                float2 bb = *(const float2*)&bv[hd + d0];
                float vx = d.x + bb.x, vy = d.y + bb.y;
                float vz = d.z + bb.x, vw = d.w + bb.y;
                float px = __shfl_xor_sync(0xFFFFFFFFu, vx, 4);
                float py = __shfl_xor_sync(0xFFFFFFFFu, vy, 4);
                float pz = __shfl_xor_sync(0xFFFFFFFFu, vz, 4);
                float pw = __shfl_xor_sync(0xFFFFFFFFu, vw, 4);
                if (!(grp & 1)) {
                    int r0  = mt * 16 + grp;
                    int j2a = r0 >> 1, j2b = j2a + 4;
                    vf[d0 * VF_S + j2a]       = pkbf(vx, px);
                    vf[(d0 + 1) * VF_S + j2a] = pkbf(vy, py);
                    vf[d0 * VF_S + j2b]       = pkbf(vz, pz);
                    vf[(d0 + 1) * VF_S + j2b] = pkbf(vw, pw);
                }
            }
        }
        {   // stage W1 (both nc) into WA
            const uint4* src = w1f4 + h * 1024;
#pragma unroll
            for (int j = 0; j < 4; j++) {
                int idx = t + j * 256;
                CPA16(smu + ((WA_OFF + idx * 4) << 2), src + idx);
            }
            CPCOMMIT();
        }
        __syncthreads();   // QF/KF/VF visible

        // ===== scores + softmax + z: half=0 warps ONLY (dedup) =====
        if (half == 0) {
            float4 Ds[8];
#pragma unroll
            for (int i = 0; i < 8; i++) Ds[i] = make_float4(0.f, 0.f, 0.f, 0.f);
#pragma unroll
            for (int ks = 0; ks < 2; ks++) {
                uint4 qa = ((const uint4*)(smw + QF_OFF))[(mt * 2 + ks) * 32 + lane];
#pragma unroll
                for (int nt = 0; nt < 8; nt++) {
                    uint2 kb = ((const uint2*)(smw + KF_OFF))[(ks * 8 + nt) * 32 + lane];
                    mma_bf16(Ds[nt], qa.x, qa.y, qa.z, qa.w, kb.x, kb.y);
                }
            }
            float m0 = Ds[0].x, m1 = Ds[0].z;
#pragma unroll
            for (int nt = 0; nt < 8; nt++) {
                m0 = fmaxf(m0, fmaxf(Ds[nt].x, Ds[nt].y));
                m1 = fmaxf(m1, fmaxf(Ds[nt].z, Ds[nt].w));
            }
            m0 = fmaxf(m0, __shfl_xor_sync(0xFFFFFFFFu, m0, 1));
            m0 = fmaxf(m0, __shfl_xor_sync(0xFFFFFFFFu, m0, 2));
            m1 = fmaxf(m1, __shfl_xor_sync(0xFFFFFFFFu, m1, 1));
            m1 = fmaxf(m1, __shfl_xor_sync(0xFFFFFFFFu, m1, 2));
            float s0 = 0.f, s1 = 0.f;
#pragma unroll
            for (int nt = 0; nt < 8; nt++) {
                Ds[nt].x = __expf(Ds[nt].x - m0);
                Ds[nt].y = __expf(Ds[nt].y - m0);
                Ds[nt].z = __expf(Ds[nt].z - m1);
                Ds[nt].w = __expf(Ds[nt].w - m1);
                s0 += Ds[nt].x + Ds[nt].y;
                s1 += Ds[nt].z + Ds[nt].w;
            }
            s0 += __shfl_xor_sync(0xFFFFFFFFu, s0, 1);
            s0 += __shfl_xor_sync(0xFFFFFFFFu, s0, 2);
            s1 += __shfl_xor_sync(0xFFFFFFFFu, s1, 1);
            s1 += __shfl_xor_sync(0xFFFFFFFFu, s1, 2);
            const float inv0 = 1.f / s0, inv1 = 1.f / s1;

            float4 Dz[4];
#pragma unroll
            for (int i = 0; i < 4; i++) Dz[i] = make_float4(0.f, 0.f, 0.f, 0.f);
            const uint32_t* vfw = smw + VF_OFF;
#pragma unroll
            for (int kz = 0; kz < 4; kz++) {
                uint32_t a0 = pkbf(Ds[2*kz].x   * inv0, Ds[2*kz].y   * inv0);
                uint32_t a1 = pkbf(Ds[2*kz].z   * inv1, Ds[2*kz].w   * inv1);
                uint32_t a2 = pkbf(Ds[2*kz+1].x * inv0, Ds[2*kz+1].y * inv0);
                uint32_t a3 = pkbf(Ds[2*kz+1].z * inv1, Ds[2*kz+1].w * inv1);
#pragma unroll
                for (int ntd = 0; ntd < 4; ntd++) {
                    uint32_t b0 = vfw[(ntd * 8 + grp) * VF_S + 8 * kz + tig];
                    uint32_t b1 = vfw[(ntd * 8 + grp) * VF_S + 8 * kz + tig + 4];
                    mma_bf16(Dz[ntd], a0, a1, a2, a3, b0, b1);
                }
            }
            // pack z -> W1 A-frags, publish to ZA
#pragma unroll
            for (int ks = 0; ks < 2; ks++) {
                uint4 za;
                za.x = pkbf(Dz[2*ks].x,   Dz[2*ks].y);
                za.y = pkbf(Dz[2*ks].z,   Dz[2*ks].w);
                za.z = pkbf(Dz[2*ks+1].x, Dz[2*ks+1].y);
                za.w = pkbf(Dz[2*ks+1].z, Dz[2*ks+1].w);
                ((uint4*)(smw + ZA_OFF))[(mt * 2 + ks) * 32 + lane] = za;
            }
        }
        CPWAIT0();
        __syncthreads();   // WA + ZA visible to all

        // ===== facc += z @ W1 (paired B loads) =====
        {
            uint4 za0 = ((const uint4*)(smw + ZA_OFF))[(mt * 2 + 0) * 32 + lane];
            uint4 za1 = ((const uint4*)(smw + ZA_OFF))[(mt * 2 + 1) * 32 + lane];
            const uint4* wa4 = (const uint4*)(smw + WA_OFF);
#pragma unroll
            for (int nc = 0; nc < 2; nc++) {
#pragma unroll
                for (int ks = 0; ks < 2; ks++) {
                    uint4 za = ks ? za1 : za0;
                    const uint4* bp = wa4 + (((nc * 2 + ks) * 8) + half * 4) * 32 + lane;
#pragma unroll
                    for (int j = 0; j < 4; j++) {
                        uint4 bb = bp[j * 32];
                        mma_bf16(facc4[nc*8 + 2*j],   za.x, za.y, za.z, za.w, bb.x, bb.y);
                        mma_bf16(facc4[nc*8 + 2*j+1], za.x, za.y, za.z, za.w, bb.z, bb.w);
                    }
                }
            }
        }
        // loop-top sync protects region reuse
    }

    // ===== epilogue: f = relu(facc + b1 + x); dot W2 (x exact from gmem) ====
    {
        const int r0 = mt * 16 + grp, r1 = r0 + 8;
        float part = 0.f;
#pragma unroll
        for (int fi = 0; fi < 16; fi++) {
            int nc = fi >> 3, nt = fi & 7;
            int n  = nc * 128 + half * 64 + nt * 8 + 2 * tig;
            float2 b1v = *(const float2*)&b1[n];
            float2 x0  = *(const float2*)&xg[r0 * DIM + n];
            float2 x1  = *(const float2*)&xg[r1 * DIM + n];
            float2 w20 = *(const float2*)&W2[r0 * DIM + n];
            float2 w21 = *(const float2*)&W2[r1 * DIM + n];
            float4 d = facc4[fi];
            float f0 = fmaxf(d.x + b1v.x + x0.x, 0.f);
            float f1 = fmaxf(d.y + b1v.y + x0.y, 0.f);
            float f2 = fmaxf(d.z + b1v.x + x1.x, 0.f);
            float f3 = fmaxf(d.w + b1v.y + x1.y, 0.f);
            part += f0 * w20.x + f1 * w20.y + f2 * w21.x + f3 * w21.y;
        }
        red[t] = part;
    }
    __syncthreads();

#pragma unroll
    for (int s = 128; s > 0; s >>= 1) {
        if (t < s) red[t] += red[t + s];
        __syncthreads();
    }
    if (t == 0) {
        out[b] = 1.f / (1.f + __expf(-(red[0] + b2[0])));
    }
}

extern "C" void kernel_launch(void* const* d_in, const int* in_sizes, int n_in,
                              void* d_out, int out_size)
{
    const float* x  = (const float*)d_in[0];
    const float* Wq = (const float*)d_in[1];
    const float* bq = (const float*)d_in[2];
    const float* Wk = (const float*)d_in[3];
    const float* bk = (const float*)d_in[4];
    const float* Wv = (const float*)d_in[5];
    const float* bv = (const float*)d_in[6];
    const float* W1 = (const float*)d_in[7];
    const float* b1 = (const float*)d_in[8];
    const float* W2 = (const float*)d_in[9];
    const float* b2 = (const float*)d_in[10];
    float* out = (float*)d_out;

    prep_kernel<<<128, 256>>>(Wq, Wk, Wv, W1);

    const int smem_bytes = SMEM_FLOATS * (int)sizeof(float); // 82,944 B -> 2 CTAs/SM
    cudaFuncSetAttribute(autoint_kernel,
                         cudaFuncAttributeMaxDynamicSharedMemorySize, smem_bytes);
    autoint_kernel<<<8192, 256, smem_bytes>>>(x, bq, bk, bv, b1, W2, b2, out);
}

// round 14
// speedup vs baseline: 3.6779x; 1.0010x over previous
#include <cuda_runtime.h>
#include <math.h>
#include <stdint.h>

#define NFEAT 64
#define DIM   256
#define NHEAD 8
#define HDIM  32

// smem word offsets (u32 words). Total 20736 words = 82,944 B -> 2 CTAs/SM.
//  axf 0..8192                 x as bf16 A-fragments (persistent)
//  proj staging PA0 8192 (6144) / PA1 14336 (6144)   [proj phase]
//  QF 8192 / KF 9216 / VF 10240 / WA 11392 / ZA 15488 [scatter..W1]
//  RED 20480..20736
#define PA0    8192
#define PA1    14336
#define QF_OFF 8192
#define KF_OFF 9216
#define VF_OFF 10240
#define VF_S   36
#define WA_OFF 11392
#define ZA_OFF 15488
#define OFF_RED 20480
#define SMEM_FLOATS 20736

// bf16 weight B-fragments, nt-PAIRED as uint4 (prep_kernel each launch)
// WPF: [h 8][ks 16][p 6][lane 32] uint4 {ntA.b0, ntA.b1, ntB.b0, ntB.b1}
// W1F: [h 8][nc 2][ks 2][p 8][lane 32] uint4
__device__ __align__(16) uint32_t WPF[8*16*6*32*4];   // 98,304 words
__device__ __align__(16) uint32_t W1F[8*2*2*8*32*4];  // 32,768 words

__device__ __forceinline__ uint32_t pkbf(float lo, float hi) {
    uint32_t r;
    asm("cvt.rn.bf16x2.f32 %0, %1, %2;" : "=r"(r) : "f"(hi), "f"(lo));
    return r;
}
__device__ __forceinline__ void mma_bf16(float4& d,
    uint32_t a0, uint32_t a1, uint32_t a2, uint32_t a3,
    uint32_t b0, uint32_t b1)
{
    asm("mma.sync.aligned.m16n8k16.row.col.f32.bf16.bf16.f32 "
        "{%0,%1,%2,%3}, {%4,%5,%6,%7}, {%8,%9}, {%0,%1,%2,%3};"
        : "+f"(d.x), "+f"(d.y), "+f"(d.z), "+f"(d.w)
        : "r"(a0), "r"(a1), "r"(a2), "r"(a3), "r"(b0), "r"(b1));
}
__device__ __forceinline__ uint32_t s2u(const void* p) {
    uint32_t a;
    asm("{ .reg .u64 t; cvta.to.shared.u64 t, %1; cvt.u32.u64 %0, t; }"
        : "=r"(a) : "l"(p));
    return a;
}
#define CPA16(dst, src) \
    asm volatile("cp.async.cg.shared.global [%0], [%1], 16;" :: "r"(dst), "l"(src))
#define CPCOMMIT() asm volatile("cp.async.commit_group;" ::: "memory")
#define CPWAIT1()  asm volatile("cp.async.wait_group 1;"  ::: "memory")
#define CPWAIT0()  asm volatile("cp.async.wait_group 0;"  ::: "memory")

// ---------------- prep: weights -> paired bf16 B-fragments ----------------
__global__ __launch_bounds__(256)
void prep_kernel(const float* __restrict__ Wq, const float* __restrict__ Wk,
                 const float* __restrict__ Wv, const float* __restrict__ W1)
{
    int id = blockIdx.x * 256 + threadIdx.x;   // 32768 uint4 slots
    if (id < 24576) {                          // WPF: [h][ks][p][lane]
        int lane = id & 31;
        int g    = id >> 5;
        int p    = g % 6;
        int ks   = (g / 6) & 15;
        int h    = g / 96;
        uint4 v;
#pragma unroll
        for (int e = 0; e < 2; e++) {
            int nt  = 2 * p + e;
            int mat = nt >> 2;
            const float* W = (mat == 0) ? Wq : (mat == 1) ? Wk : Wv;
            int n  = h * HDIM + (nt & 3) * 8 + (lane >> 2);
            int k0 = ks * 16 + (lane & 3) * 2;
            uint32_t b0 = pkbf(W[k0 * DIM + n],       W[(k0 + 1) * DIM + n]);
            uint32_t b1 = pkbf(W[(k0 + 8) * DIM + n], W[(k0 + 9) * DIM + n]);
            if (e == 0) { v.x = b0; v.y = b1; } else { v.z = b0; v.w = b1; }
        }
        ((uint4*)WPF)[id] = v;
    } else {                                   // W1F: [h][nc][ks][p][lane]
        int j    = id - 24576;
        int lane = j & 31;
        int g    = j >> 5;
        int p    = g & 7;
        int ks   = (g >> 3) & 1;
        int nc   = (g >> 4) & 1;
        int h    = g >> 5;
        uint4 v;
#pragma unroll
        for (int e = 0; e < 2; e++) {
            int nt = 2 * p + e;                // 0..15
            int n  = nc * 128 + nt * 8 + (lane >> 2);
            int k0 = h * HDIM + ks * 16 + (lane & 3) * 2;
            uint32_t b0 = pkbf(W1[k0 * DIM + n],       W1[(k0 + 1) * DIM + n]);
            uint32_t b1 = pkbf(W1[(k0 + 8) * DIM + n], W1[(k0 + 9) * DIM + n]);
            if (e == 0) { v.x = b0; v.y = b1; } else { v.z = b0; v.w = b1; }
        }
        ((uint4*)W1F)[j] = v;
    }
}

// ---------------- main ----------------
__global__ __launch_bounds__(256, 2)
void autoint_kernel(const float* __restrict__ x,
                    const float* __restrict__ bq, const float* __restrict__ bk,
                    const float* __restrict__ bv, const float* __restrict__ b1,
                    const float* __restrict__ W2, const float* __restrict__ b2,
                    float* __restrict__ out)
{
    extern __shared__ float sm[];
    uint32_t* smw = (uint32_t*)sm;
    float* red = sm + OFF_RED;
    const uint32_t smu = s2u(sm);

    const int t = threadIdx.x;
    const int b = blockIdx.x;
    const float* xg = x + (size_t)b * (NFEAT * DIM);

    const int lane = t & 31;
    const int grp  = lane >> 2;
    const int tig  = lane & 3;
    const int w    = t >> 5;
    const int mt   = w & 3;
    const int half = w >> 2;
    const float isd = 0.17677669529663687f;   // 1/sqrt(32)

    // ---- phase 0: x -> bf16 A-fragment order ----
    {
        const float4* xg4 = (const float4*)xg;
#pragma unroll
        for (int n = t; n < NFEAT * DIM / 4; n += 256) {
            float4 v = xg4[n];
            int r   = n >> 6;
            int c4  = (n & 63) << 2;
            int rmt = r >> 4, rgr = r & 7, hi8 = (r >> 3) & 1;
            int ks  = c4 >> 4, koff = c4 & 15;
            int hi  = koff >> 3, tg0 = (koff >> 1) & 3;
            int comp = hi8 + (hi << 1);
            uint32_t* d = smw + (((rmt * 16 + ks) * 32 + rgr * 4) << 2) + comp;
            d[tg0 * 4]       = pkbf(v.x, v.y);
            d[(tg0 + 1) * 4] = pkbf(v.z, v.w);
        }
    }

    float4 facc4[16];
#pragma unroll
    for (int i = 0; i < 16; i++) facc4[i] = make_float4(0.f, 0.f, 0.f, 0.f);

    const uint4* wpf4 = (const uint4*)WPF;   // 3072 uint4 per h; 1536 per chunk
    const uint4* w1f4 = (const uint4*)W1F;   // 1024 uint4 per h

    for (int h = 0; h < NHEAD; h++) {
        const int hd = h * HDIM;
        __syncthreads();   // frag/staging regions free; axf visible (h=0)

        // ===== QKV projection: 2 chunks of 8 ksteps, double-buffered =====
#pragma unroll
        for (int c = 0; c < 2; c++) {
            const uint4* src = wpf4 + h * 3072 + c * 1536;
            const int bofs = c ? PA1 : PA0;
#pragma unroll
            for (int j = 0; j < 6; j++) {
                int idx = t + j * 256;
                CPA16(smu + ((bofs + idx * 4) << 2), src + idx);
            }
            CPCOMMIT();
        }

        float4 D[6];
#pragma unroll
        for (int i = 0; i < 6; i++) D[i] = make_float4(0.f, 0.f, 0.f, 0.f);

#pragma unroll
        for (int ch = 0; ch < 2; ch++) {
            if (ch == 0) { CPWAIT1(); } else { CPWAIT0(); }
            __syncthreads();
            const uint4* bw4 = (const uint4*)(smw + (ch ? PA1 : PA0));
#pragma unroll
            for (int ksl = 0; ksl < 8; ksl++) {
                int ks = ch * 8 + ksl;
                uint4 av = ((const uint4*)smw)[(mt * 16 + ks) * 32 + lane];
                const uint4* bp = bw4 + (ksl * 6 + half * 3) * 32 + lane;
#pragma unroll
                for (int j = 0; j < 3; j++) {
                    uint4 bb = bp[j * 32];
                    mma_bf16(D[2*j],   av.x, av.y, av.z, av.w, bb.x, bb.y);
                    mma_bf16(D[2*j+1], av.x, av.y, av.z, av.w, bb.z, bb.w);
                }
            }
        }
        __syncthreads();   // proj reads done -> frag regions writable

        // ===== scatter q->A-frags, k/v->B-frags; stage W1 (single region) ==
        if (half == 0) {
#pragma unroll
            for (int ks = 0; ks < 2; ks++) {
                float4 dA = D[2 * ks];
                float4 dB = D[2 * ks + 1];
                float2 bA = *(const float2*)&bq[hd + ks * 16 + 2 * tig];
                float2 bB = *(const float2*)&bq[hd + ks * 16 + 8 + 2 * tig];
                uint4 qa;
                qa.x = pkbf((dA.x + bA.x) * isd, (dA.y + bA.y) * isd);
                qa.y = pkbf((dA.z + bA.x) * isd, (dA.w + bA.y) * isd);
                qa.z = pkbf((dB.x + bB.x) * isd, (dB.y + bB.y) * isd);
                qa.w = pkbf((dB.z + bB.x) * isd, (dB.w + bB.y) * isd);
                ((uint4*)(smw + QF_OFF))[(mt * 2 + ks) * 32 + lane] = qa;
            }
#pragma unroll
            for (int nt = 4; nt < 6; nt++) {       // k cols 0..15
                float4 d = D[nt];
                int base = (nt - 4) * 8;
                float2 bb = *(const float2*)&bk[hd + base + 2 * tig];
                int breg = (nt == 5);
                uint32_t* kf = smw + KF_OFF;
                int i0 = (((0 * 8 + mt * 2) * 32 + grp * 4 + tig) << 1) + breg;
                int i1 = (((0 * 8 + mt * 2 + 1) * 32 + grp * 4 + tig) << 1) + breg;
                kf[i0] = pkbf(d.x + bb.x, d.y + bb.y);
                kf[i1] = pkbf(d.z + bb.x, d.w + bb.y);
            }
        } else {
#pragma unroll
            for (int nt = 0; nt < 2; nt++) {       // k cols 16..31
                float4 d = D[nt];
                int base = 16 + nt * 8;
                float2 bb = *(const float2*)&bk[hd + base + 2 * tig];
                int breg = nt;
                uint32_t* kf = smw + KF_OFF;
                int i0 = (((1 * 8 + mt * 2) * 32 + grp * 4 + tig) << 1) + breg;
                int i1 = (((1 * 8 + mt * 2 + 1) * 32 + grp * 4 + tig) << 1) + breg;
                kf[i0] = pkbf(d.x + bb.x, d.y + bb.y);
                kf[i1] = pkbf(d.z + bb.x, d.w + bb.y);
            }
            uint32_t* vf = smw + VF_OFF;
#pragma unroll
            for (int nt = 2; nt < 6; nt++) {       // v cols 0..31
                float4 d = D[nt];
                int d0 = (nt - 2) * 8 + 2 * tig;
                float2 bb = *(const float2*)&bv[hd + d0];
                float vx = d.x + bb.x, vy = d.y + bb.y;
                float vz = d.z + bb.x, vw = d.w + bb.y;
                float px = __shfl_xor_sync(0xFFFFFFFFu, vx, 4);
                float py = __shfl_xor_sync(0xFFFFFFFFu, vy, 4);
                float pz = __shfl_xor_sync(0xFFFFFFFFu, vz, 4);
                float pw = __shfl_xor_sync(0xFFFFFFFFu, vw, 4);
                if (!(grp & 1)) {
                    int r0  = mt * 16 + grp;
                    int j2a = r0 >> 1, j2b = j2a + 4;
                    vf[d0 * VF_S + j2a]       = pkbf(vx, px);
                    vf[(d0 + 1) * VF_S + j2a] = pkbf(vy, py);
                    vf[d0 * VF_S + j2b]       = pkbf(vz, pz);
                    vf[(d0 + 1) * VF_S + j2b] = pkbf(vw, pw);
                }
            }
        }
        {   // stage W1 (both nc) into WA
            const uint4* src = w1f4 + h * 1024;
#pragma unroll
            for (int j = 0; j < 4; j++) {
                int idx = t + j * 256;
                CPA16(smu + ((WA_OFF + idx * 4) << 2), src + idx);
            }
            CPCOMMIT();
        }
        __syncthreads();   // QF/KF/VF visible

        // ===== scores + softmax + z: half=0 warps ONLY (dedup) =====
        if (half == 0) {
            float4 Ds[8];
#pragma unroll
            for (int i = 0; i < 8; i++) Ds[i] = make_float4(0.f, 0.f, 0.f, 0.f);
#pragma unroll
            for (int ks = 0; ks < 2; ks++) {
                uint4 qa = ((const uint4*)(smw + QF_OFF))[(mt * 2 + ks) * 32 + lane];
#pragma unroll
                for (int nt = 0; nt < 8; nt++) {
                    uint2 kb = ((const uint2*)(smw + KF_OFF))[(ks * 8 + nt) * 32 + lane];
                    mma_bf16(Ds[nt], qa.x, qa.y, qa.z, qa.w, kb.x, kb.y);
                }
            }
            float m0 = Ds[0].x, m1 = Ds[0].z;
#pragma unroll
            for (int nt = 0; nt < 8; nt++) {
                m0 = fmaxf(m0, fmaxf(Ds[nt].x, Ds[nt].y));
                m1 = fmaxf(m1, fmaxf(Ds[nt].z, Ds[nt].w));
            }
            m0 = fmaxf(m0, __shfl_xor_sync(0xFFFFFFFFu, m0, 1));
            m0 = fmaxf(m0, __shfl_xor_sync(0xFFFFFFFFu, m0, 2));
            m1 = fmaxf(m1, __shfl_xor_sync(0xFFFFFFFFu, m1, 1));
            m1 = fmaxf(m1, __shfl_xor_sync(0xFFFFFFFFu, m1, 2));
            float s0 = 0.f, s1 = 0.f;
#pragma unroll
            for (int nt = 0; nt < 8; nt++) {
                Ds[nt].x = __expf(Ds[nt].x - m0);
                Ds[nt].y = __expf(Ds[nt].y - m0);
                Ds[nt].z = __expf(Ds[nt].z - m1);
                Ds[nt].w = __expf(Ds[nt].w - m1);
                s0 += Ds[nt].x + Ds[nt].y;
                s1 += Ds[nt].z + Ds[nt].w;
            }
            s0 += __shfl_xor_sync(0xFFFFFFFFu, s0, 1);
            s0 += __shfl_xor_sync(0xFFFFFFFFu, s0, 2);
            s1 += __shfl_xor_sync(0xFFFFFFFFu, s1, 1);
            s1 += __shfl_xor_sync(0xFFFFFFFFu, s1, 2);
            const float inv0 = 1.f / s0, inv1 = 1.f / s1;

            float4 Dz[4];
#pragma unroll
            for (int i = 0; i < 4; i++) Dz[i] = make_float4(0.f, 0.f, 0.f, 0.f);
            const uint32_t* vfw = smw + VF_OFF;
#pragma unroll
            for (int kz = 0; kz < 4; kz++) {
                uint32_t a0 = pkbf(Ds[2*kz].x   * inv0, Ds[2*kz].y   * inv0);
                uint32_t a1 = pkbf(Ds[2*kz].z   * inv1, Ds[2*kz].w   * inv1);
                uint32_t a2 = pkbf(Ds[2*kz+1].x * inv0, Ds[2*kz+1].y * inv0);
                uint32_t a3 = pkbf(Ds[2*kz+1].z * inv1, Ds[2*kz+1].w * inv1);
#pragma unroll
                for (int ntd = 0; ntd < 4; ntd++) {
                    uint32_t b0 = vfw[(ntd * 8 + grp) * VF_S + 8 * kz + tig];
                    uint32_t b1 = vfw[(ntd * 8 + grp) * VF_S + 8 * kz + tig + 4];
                    mma_bf16(Dz[ntd], a0, a1, a2, a3, b0, b1);
                }
            }
            // pack z -> W1 A-frags, publish to ZA
#pragma unroll
            for (int ks = 0; ks < 2; ks++) {
                uint4 za;
                za.x = pkbf(Dz[2*ks].x,   Dz[2*ks].y);
                za.y = pkbf(Dz[2*ks].z,   Dz[2*ks].w);
                za.z = pkbf(Dz[2*ks+1].x, Dz[2*ks+1].y);
                za.w = pkbf(Dz[2*ks+1].z, Dz[2*ks+1].w);
                ((uint4*)(smw + ZA_OFF))[(mt * 2 + ks) * 32 + lane] = za;
            }
        }
        CPWAIT0();
        __syncthreads();   // WA + ZA visible to all

        // ===== facc += z @ W1 (paired B loads) =====
        {
            uint4 za0 = ((const uint4*)(smw + ZA_OFF))[(mt * 2 + 0) * 32 + lane];
            uint4 za1 = ((const uint4*)(smw + ZA_OFF))[(mt * 2 + 1) * 32 + lane];
            const uint4* wa4 = (const uint4*)(smw + WA_OFF);
#pragma unroll
            for (int nc = 0; nc < 2; nc++) {
#pragma unroll
                for (int ks = 0; ks < 2; ks++) {
                    uint4 za = ks ? za1 : za0;
                    const uint4* bp = wa4 + (((nc * 2 + ks) * 8) + half * 4) * 32 + lane;
#pragma unroll
                    for (int j = 0; j < 4; j++) {
                        uint4 bb = bp[j * 32];
                        mma_bf16(facc4[nc*8 + 2*j],   za.x, za.y, za.z, za.w, bb.x, bb.y);
                        mma_bf16(facc4[nc*8 + 2*j+1], za.x, za.y, za.z, za.w, bb.z, bb.w);
                    }
                }
            }
        }
        // loop-top sync protects region reuse
    }

    // ===== epilogue: f = relu(facc + b1 + x); dot W2 (x exact from gmem) ====
    {
        const int r0 = mt * 16 + grp, r1 = r0 + 8;
        float part = 0.f;
#pragma unroll
        for (int fi = 0; fi < 16; fi++) {
            int nc = fi >> 3, nt = fi & 7;
            int n  = nc * 128 + half * 64 + nt * 8 + 2 * tig;
            float2 b1v = *(const float2*)&b1[n];
            float2 x0  = *(const float2*)&xg[r0 * DIM + n];
            float2 x1  = *(const float2*)&xg[r1 * DIM + n];
            float2 w20 = *(const float2*)&W2[r0 * DIM + n];
            float2 w21 = *(const float2*)&W2[r1 * DIM + n];
            float4 d = facc4[fi];
            float f0 = fmaxf(d.x + b1v.x + x0.x, 0.f);
            float f1 = fmaxf(d.y + b1v.y + x0.y, 0.f);
            float f2 = fmaxf(d.z + b1v.x + x1.x, 0.f);
            float f3 = fmaxf(d.w + b1v.y + x1.y, 0.f);
            part += f0 * w20.x + f1 * w20.y + f2 * w21.x + f3 * w21.y;
        }
        red[t] = part;
    }
    __syncthreads();

#pragma unroll
    for (int s = 128; s > 0; s >>= 1) {
        if (t < s) red[t] += red[t + s];
        __syncthreads();
    }
    if (t == 0) {
        out[b] = 1.f / (1.f + __expf(-(red[0] + b2[0])));
    }
}

extern "C" void kernel_launch(void* const* d_in, const int* in_sizes, int n_in,
                              void* d_out, int out_size)
{
    const float* x  = (const float*)d_in[0];
    const float* Wq = (const float*)d_in[1];
    const float* bq = (const float*)d_in[2];
    const float* Wk = (const float*)d_in[3];
    const float* bk = (const float*)d_in[4];
    const float* Wv = (const float*)d_in[5];
    const float* bv = (const float*)d_in[6];
    const float* W1 = (const float*)d_in[7];
    const float* b1 = (const float*)d_in[8];
    const float* W2 = (const float*)d_in[9];
    const float* b2 = (const float*)d_in[10];
    float* out = (float*)d_out;

    prep_kernel<<<128, 256>>>(Wq, Wk, Wv, W1);

    const int smem_bytes = SMEM_FLOATS * (int)sizeof(float); // 82,944 B -> 2 CTAs/SM
    cudaFuncSetAttribute(autoint_kernel,
                         cudaFuncAttributeMaxDynamicSharedMemorySize, smem_bytes);
    autoint_kernel<<<8192, 256, smem_bytes>>>(x, bq, bk, bv, b1, W2, b2, out);
}